// round 1
// baseline (speedup 1.0000x reference)
#include <cuda_runtime.h>
#include <math.h>

#define BATCH 2
#define SEQ   1024
#define EMB   1024
#define NH    16
#define HS    64
#define BD    16
#define DELTA 64
#define TTILE 16
#define NROWS (TTILE + DELTA - 1)   // 79

// ---------------- scratch (static device memory; no allocs) ----------------
__device__ float g_disp[BATCH * SEQ * NH * BD];   // (b*SEQ+t)*256 + h*16 + d
__device__ float g_val [BATCH * SEQ * EMB];       // (b*SEQ+t)*1024 + h*64 + e
__device__ float g_att [BATCH * SEQ * EMB];       // attention output pre-cproj
__device__ float g_pos [DELTA * BD];              // rel_pos_emb @ W_pos

// ---------------- GEMM: C[M,N] = A[M,K] * B[K,N], row-major --------------
#define GBM 128
#define GBN 64
#define GBK 16

__global__ __launch_bounds__(256) void sgemm_kernel(
    const float* __restrict__ A, const float* __restrict__ B,
    float* __restrict__ C, int M, int N, int K)
{
    __shared__ float sA[GBK][GBM + 1];   // transposed A tile, padded
    __shared__ float sB[GBK][GBN];

    const int tid = threadIdx.x;
    const int bm = blockIdx.y * GBM;
    const int bn = blockIdx.x * GBN;
    const int tx = tid & 15;   // N direction (x4)
    const int ty = tid >> 4;   // M direction (x8)

    float acc[8][4];
#pragma unroll
    for (int i = 0; i < 8; i++)
#pragma unroll
        for (int j = 0; j < 4; j++) acc[i][j] = 0.f;

    for (int k0 = 0; k0 < K; k0 += GBK) {
#pragma unroll
        for (int q = 0; q < 2; q++) {
            int l = tid + q * 256;
            int r = l >> 2;
            int c4 = (l & 3) * 4;
            float4 v = *(const float4*)(A + (size_t)(bm + r) * K + k0 + c4);
            sA[c4 + 0][r] = v.x;
            sA[c4 + 1][r] = v.y;
            sA[c4 + 2][r] = v.z;
            sA[c4 + 3][r] = v.w;
        }
        {
            int kk = tid >> 4;
            int n4 = (tid & 15) * 4;
            *(float4*)(&sB[kk][n4]) = *(const float4*)(B + (size_t)(k0 + kk) * N + bn + n4);
        }
        __syncthreads();

#pragma unroll
        for (int k = 0; k < GBK; k++) {
            float a[8];
#pragma unroll
            for (int i = 0; i < 8; i++) a[i] = sA[k][ty * 8 + i];
            float4 bv = *(const float4*)(&sB[k][tx * 4]);
            float bf[4] = {bv.x, bv.y, bv.z, bv.w};
#pragma unroll
            for (int i = 0; i < 8; i++)
#pragma unroll
                for (int j = 0; j < 4; j++)
                    acc[i][j] = fmaf(a[i], bf[j], acc[i][j]);
        }
        __syncthreads();
    }

#pragma unroll
    for (int i = 0; i < 8; i++) {
        float4 v = make_float4(acc[i][0], acc[i][1], acc[i][2], acc[i][3]);
        *(float4*)(C + (size_t)(bm + ty * 8 + i) * N + bn + tx * 4) = v;
    }
}

// ---------------- pos_term = rel_pos_emb @ W_pos  (64x16) ----------------
__global__ void pos_kernel(const float* __restrict__ rel, const float* __restrict__ Wp)
{
    int i = threadIdx.x;
    if (i < DELTA * BD) {
        int j = i >> 4, c = i & 15;
        float s = 0.f;
#pragma unroll
        for (int k = 0; k < BD; k++)
            s = fmaf(rel[j * BD + k], Wp[k * BD + c], s);
        g_pos[i] = s;
    }
}

// ---------------- fused window attention ----------------
__device__ __forceinline__ float dot16(const float* sm, const float* wc)
{
    const float4* p = (const float4*)sm;
    float4 d0 = p[0], d1 = p[1], d2 = p[2], d3 = p[3];
    float s;
    s = d0.x * wc[0];
    s = fmaf(d0.y, wc[1], s);
    s = fmaf(d0.z, wc[2], s);
    s = fmaf(d0.w, wc[3], s);
    s = fmaf(d1.x, wc[4], s);
    s = fmaf(d1.y, wc[5], s);
    s = fmaf(d1.z, wc[6], s);
    s = fmaf(d1.w, wc[7], s);
    s = fmaf(d2.x, wc[8], s);
    s = fmaf(d2.y, wc[9], s);
    s = fmaf(d2.z, wc[10], s);
    s = fmaf(d2.w, wc[11], s);
    s = fmaf(d3.x, wc[12], s);
    s = fmaf(d3.y, wc[13], s);
    s = fmaf(d3.z, wc[14], s);
    s = fmaf(d3.w, wc[15], s);
    return s;
}

__global__ __launch_bounds__(512) void fused_kernel(
    const float* __restrict__ W_strain, const float* __restrict__ W_dmg,
    const float* __restrict__ b_dmg,    const float* __restrict__ W_bond,
    const float* __restrict__ W_dmg_out, const float* __restrict__ b_dmg_out)
{
    __shared__ float s_val [NROWS * HS];
    __shared__ float s_disp[NROWS * BD];
    __shared__ float s_pos [DELTA * BD];

    const int b  = blockIdx.z;
    const int h  = blockIdx.y;
    const int t0 = blockIdx.x * TTILE;
    const int tid = threadIdx.x;
    const int base_s = t0 - (DELTA - 1);

    // load val window: 79 rows x 64 floats
    for (int i = tid; i < NROWS * (HS / 4); i += 512) {
        int r  = i >> 4;           // 16 float4 per row
        int c4 = (i & 15) * 4;
        int s  = base_s + r;
        float4 v = make_float4(0.f, 0.f, 0.f, 0.f);
        if (s >= 0)
            v = *(const float4*)(g_val + (size_t)(b * SEQ + s) * EMB + h * HS + c4);
        *(float4*)(s_val + r * HS + c4) = v;
    }
    // load disp window: 79 rows x 16 floats
    for (int i = tid; i < NROWS * (BD / 4); i += 512) {
        int r  = i >> 2;
        int c4 = (i & 3) * 4;
        int s  = base_s + r;
        float4 v = make_float4(0.f, 0.f, 0.f, 0.f);
        if (s >= 0)
            v = *(const float4*)(g_disp + (size_t)(b * SEQ + s) * (NH * BD) + h * BD + c4);
        *(float4*)(s_disp + r * BD + c4) = v;
    }
    // pos_term
    for (int i = tid; i < (DELTA * BD) / 4; i += 512) {
        *(float4*)(s_pos + i * 4) = *(const float4*)(g_pos + i * 4);
    }
    __syncthreads();

    const int wid  = tid >> 5;
    const int lane = tid & 31;
    const int g    = lane >> 4;    // 0: bond path, 1: damage path
    const int c    = lane & 15;    // output channel
    const int t    = t0 + wid;

    // per-lane weight column (registers, L1-cached loads, once)
    const float* Wm = g ? W_dmg : W_strain;
    float wc[BD];
#pragma unroll
    for (int k = 0; k < BD; k++) wc[k] = Wm[k * BD + c];
    const float wout = g ? W_dmg_out[c] : W_bond[c];
    const float addc = g ? b_dmg[c] : 0.f;
    const float bout = b_dmg_out[0];

    // hoisted disp_t @ Wcol
    const int rt = wid + (DELTA - 1);
    const float precomp = dot16(s_disp + rt * BD, wc);

    int jstart = (DELTA - 1) - t;
    if (jstart < 0) jstart = 0;

    float m = -1e30f, ssum = 0.f, acc0 = 0.f, acc1 = 0.f;

    for (int j = jstart; j < DELTA; j++) {
        const int r = wid + j;
        float dot = dot16(s_disp + r * BD, wc);
        float padd = s_pos[j * BD + c];
        float xx = dot - precomp + (g ? addc : padd);
        // exact gelu (erf-based)
        float act = 0.5f * xx * (1.0f + erff(xx * 0.70710678118654752440f));
        float v = act * wout;
        // reduce over 16-lane group (both groups simultaneously)
#pragma unroll
        for (int off = 1; off < 16; off <<= 1)
            v += __shfl_xor_sync(0xffffffffu, v, off);
        float other = __shfl_xor_sync(0xffffffffu, v, 16);
        float bond = g ? other : v;
        float dm   = g ? v : other;
        float dmg  = 1.0f / (1.0f + __expf(-(dm + bout)));
        float logit = bond - 10.0f * dmg;

        // online softmax + weighted val accumulation
        float nm    = fmaxf(m, logit);
        float scale = __expf(m - nm);
        float p     = __expf(logit - nm);
        ssum = ssum * scale + p;
        float v0 = s_val[r * HS + lane];
        float v1 = s_val[r * HS + 32 + lane];
        acc0 = fmaf(p, v0, acc0 * scale);
        acc1 = fmaf(p, v1, acc1 * scale);
        m = nm;
    }

    float inv = 1.0f / ssum;
    size_t ob = (size_t)(b * SEQ + t) * EMB + h * HS;
    g_att[ob + lane]      = acc0 * inv;
    g_att[ob + 32 + lane] = acc1 * inv;
}

// ---------------- launch ----------------
extern "C" void kernel_launch(void* const* d_in, const int* in_sizes, int n_in,
                              void* d_out, int out_size)
{
    const float* x         = (const float*)d_in[0];
    const float* W_disp    = (const float*)d_in[1];
    const float* W_val     = (const float*)d_in[2];
    const float* rel       = (const float*)d_in[3];
    const float* W_strain  = (const float*)d_in[4];
    const float* W_pos     = (const float*)d_in[5];
    const float* W_bond    = (const float*)d_in[6];
    const float* W_dmg     = (const float*)d_in[7];
    const float* b_dmg     = (const float*)d_in[8];
    const float* W_dmg_out = (const float*)d_in[9];
    const float* b_dmg_out = (const float*)d_in[10];
    const float* W_cproj   = (const float*)d_in[11];
    float* out = (float*)d_out;

    float *disp_p, *val_p, *att_p;
    cudaGetSymbolAddress((void**)&disp_p, g_disp);
    cudaGetSymbolAddress((void**)&val_p,  g_val);
    cudaGetSymbolAddress((void**)&att_p,  g_att);

    const int M = BATCH * SEQ;   // 2048

    pos_kernel<<<1, 1024>>>(rel, W_pos);
    sgemm_kernel<<<dim3((NH * BD) / GBN, M / GBM), 256>>>(x, W_disp, disp_p, M, NH * BD, EMB);
    sgemm_kernel<<<dim3(EMB / GBN, M / GBM), 256>>>(x, W_val, val_p, M, EMB, EMB);
    fused_kernel<<<dim3(SEQ / TTILE, NH, BATCH), 512>>>(W_strain, W_dmg, b_dmg,
                                                        W_bond, W_dmg_out, b_dmg_out);
    sgemm_kernel<<<dim3(EMB / GBN, M / GBM), 256>>>(att_p, W_cproj, out, M, EMB, EMB);
}

// round 2
// speedup vs baseline: 1.3830x; 1.3830x over previous
#include <cuda_runtime.h>
#include <math.h>

#define BATCH 2
#define SEQ   1024
#define EMB   1024
#define NH    16
#define HS    64
#define BD    16
#define DELTA 64
#define TTILE 16
#define NROWS (TTILE + DELTA - 1)   // 79

// ---------------- scratch (static device memory; no allocs) ----------------
__device__ float g_disp[BATCH * SEQ * NH * BD];
__device__ float g_val [BATCH * SEQ * EMB];
__device__ float g_att [BATCH * SEQ * EMB];
__device__ float g_pos [DELTA * BD];

// ---------------- f32x2 helpers ----------------
__device__ __forceinline__ unsigned long long dupf(float v) {
    unsigned long long r;
    asm("mov.b64 %0, {%1, %1};" : "=l"(r) : "f"(v));
    return r;
}
__device__ __forceinline__ void ffma2(float2& d, unsigned long long a, unsigned long long b) {
    unsigned long long dd = *reinterpret_cast<unsigned long long*>(&d);
    asm("fma.rn.f32x2 %0, %1, %2, %0;" : "+l"(dd) : "l"(a), "l"(b));
    d = *reinterpret_cast<float2*>(&dd);
}
__device__ __forceinline__ float tanh_approx(float x) {
    float r;
    asm("tanh.approx.f32 %0, %1;" : "=f"(r) : "f"(x));
    return r;
}
__device__ __forceinline__ float rcp_approx(float x) {
    float r;
    asm("rcp.approx.f32 %0, %1;" : "=f"(r) : "f"(x));
    return r;
}

// ---------------- GEMM: C[M,N] = A[M,K] * B[K,N], row-major, FFMA2 --------
#define GBM 128
#define GBN 64
#define GBK 16

__global__ __launch_bounds__(256) void sgemm_kernel(
    const float* __restrict__ A, const float* __restrict__ B,
    float* __restrict__ C, int M, int N, int K)
{
    __shared__ float sA[GBK][GBM + 2];   // transposed A tile, even padding (8B align)
    __shared__ float sB[GBK][GBN];

    const int tid = threadIdx.x;
    const int bm = blockIdx.y * GBM;
    const int bn = blockIdx.x * GBN;
    const int tx = tid & 15;   // N direction (x4)
    const int ty = tid >> 4;   // M direction (x8, paired)

    float2 acc[4][4];
#pragma unroll
    for (int i = 0; i < 4; i++)
#pragma unroll
        for (int j = 0; j < 4; j++) acc[i][j] = make_float2(0.f, 0.f);

    for (int k0 = 0; k0 < K; k0 += GBK) {
#pragma unroll
        for (int q = 0; q < 2; q++) {
            int l = tid + q * 256;
            int r = l >> 2;
            int c4 = (l & 3) * 4;
            float4 v = *(const float4*)(A + (size_t)(bm + r) * K + k0 + c4);
            sA[c4 + 0][r] = v.x;
            sA[c4 + 1][r] = v.y;
            sA[c4 + 2][r] = v.z;
            sA[c4 + 3][r] = v.w;
        }
        {
            int kk = tid >> 4;
            int n4 = (tid & 15) * 4;
            *(float4*)(&sB[kk][n4]) = *(const float4*)(B + (size_t)(k0 + kk) * N + bn + n4);
        }
        __syncthreads();

#pragma unroll
        for (int k = 0; k < GBK; k++) {
            unsigned long long a2[4];
#pragma unroll
            for (int i = 0; i < 4; i++)
                a2[i] = *(const unsigned long long*)(&sA[k][ty * 8 + 2 * i]);
            float4 bv = *(const float4*)(&sB[k][tx * 4]);
            unsigned long long bb[4];
            bb[0] = dupf(bv.x); bb[1] = dupf(bv.y);
            bb[2] = dupf(bv.z); bb[3] = dupf(bv.w);
#pragma unroll
            for (int i = 0; i < 4; i++)
#pragma unroll
                for (int j = 0; j < 4; j++)
                    ffma2(acc[i][j], a2[i], bb[j]);
        }
        __syncthreads();
    }

#pragma unroll
    for (int i = 0; i < 4; i++) {
        float4 lo = make_float4(acc[i][0].x, acc[i][1].x, acc[i][2].x, acc[i][3].x);
        float4 hi = make_float4(acc[i][0].y, acc[i][1].y, acc[i][2].y, acc[i][3].y);
        *(float4*)(C + (size_t)(bm + ty * 8 + 2 * i)     * N + bn + tx * 4) = lo;
        *(float4*)(C + (size_t)(bm + ty * 8 + 2 * i + 1) * N + bn + tx * 4) = hi;
    }
}

// ---------------- pos_term = rel_pos_emb @ W_pos  (64x16) ----------------
__global__ void pos_kernel(const float* __restrict__ rel, const float* __restrict__ Wp)
{
    int i = threadIdx.x;
    if (i < DELTA * BD) {
        int j = i >> 4, c = i & 15;
        float s = 0.f;
#pragma unroll
        for (int k = 0; k < BD; k++)
            s = fmaf(rel[j * BD + k], Wp[k * BD + c], s);
        g_pos[i] = s;
    }
}

// ---------------- fused window attention ----------------
__global__ __launch_bounds__(512) void fused_kernel(
    const float* __restrict__ W_strain, const float* __restrict__ W_dmg,
    const float* __restrict__ b_dmg,    const float* __restrict__ W_bond,
    const float* __restrict__ W_dmg_out, const float* __restrict__ b_dmg_out)
{
    __shared__ __align__(16) float s_val [NROWS * HS];   // 20.2KB
    __shared__ float s_disp[NROWS * BD];                 // 5KB
    __shared__ float s_W   [BD * 32];                    // 2KB  [k][c] c<16:strain, c>=16:dmg
    __shared__ float s_P   [NROWS * 32];                 // 10.1KB precomputed dots
    __shared__ float s_pos2[DELTA * 32];                 // 8KB  [j][c] c<16:pos, c>=16:b_dmg

    const int b  = blockIdx.z;
    const int h  = blockIdx.y;
    const int t0 = blockIdx.x * TTILE;
    const int tid = threadIdx.x;
    const int base_s = t0 - (DELTA - 1);

    // ---- stage A: loads ----
    for (int i = tid; i < NROWS * (HS / 4); i += 512) {
        int r  = i >> 4;
        int c4 = (i & 15) * 4;
        int s  = base_s + r;
        float4 v = make_float4(0.f, 0.f, 0.f, 0.f);
        if (s >= 0)
            v = *(const float4*)(g_val + (size_t)(b * SEQ + s) * EMB + h * HS + c4);
        *(float4*)(s_val + r * HS + c4) = v;
    }
    for (int i = tid; i < NROWS * (BD / 4); i += 512) {
        int r  = i >> 2;
        int c4 = (i & 3) * 4;
        int s  = base_s + r;
        float4 v = make_float4(0.f, 0.f, 0.f, 0.f);
        if (s >= 0)
            v = *(const float4*)(g_disp + (size_t)(b * SEQ + s) * (NH * BD) + h * BD + c4);
        *(float4*)(s_disp + r * BD + c4) = v;
    }
    if (tid < BD * 32) {
        int k = tid >> 5, c = tid & 31;
        s_W[tid] = (c < 16) ? W_strain[k * BD + c] : W_dmg[k * BD + (c - 16)];
    }
    for (int i = tid; i < DELTA * 32; i += 512) {
        int j = i >> 5, c = i & 31;
        s_pos2[i] = (c < 16) ? g_pos[j * BD + c] : b_dmg[c - 16];
    }
    __syncthreads();

    // ---- stage B: P[r][c] = disp_window[r] . W_col[c] ----
    for (int i = tid; i < NROWS * 32; i += 512) {
        int r = i >> 5, c = i & 31;
        float s = 0.f;
#pragma unroll
        for (int k = 0; k < BD; k++)
            s = fmaf(s_disp[r * BD + k], s_W[k * 32 + c], s);
        s_P[i] = s;
    }
    __syncthreads();

    // ---- stage C: windowed softmax-attention ----
    const int wid  = tid >> 5;
    const int lane = tid & 31;
    const int g    = lane >> 4;
    const int c    = lane & 15;
    const int t    = t0 + wid;

    const float wout = g ? W_dmg_out[c] : W_bond[c];
    const float bout = b_dmg_out[0];
    const float negpre = -s_P[(wid + (DELTA - 1)) * 32 + lane];

    int jstart = (DELTA - 1) - t;
    if (jstart < 0) jstart = 0;

    float ssum = 0.f;
    float2 accv = make_float2(0.f, 0.f);

#pragma unroll 2
    for (int j = jstart; j < DELTA; j++) {
        const int r = wid + j;
        float xx = s_P[r * 32 + lane] + s_pos2[j * 32 + lane] + negpre;
        // tanh-form gelu (inputs |xx| << 1, matches erf-gelu to ~1e-6 here)
        float u    = xx * xx;
        float targ = xx * fmaf(u, 0.0356774081f, 0.7978845608f);
        float th   = tanh_approx(targ);
        float hx   = 0.5f * xx;
        float act  = fmaf(hx, th, hx);
        float v    = act * wout;
#pragma unroll
        for (int off = 1; off < 16; off <<= 1)
            v += __shfl_xor_sync(0xffffffffu, v, off);
        float other = __shfl_xor_sync(0xffffffffu, v, 16);
        float bond = g ? other : v;
        float dm   = g ? v : other;
        float e    = __expf(-dm - bout);
        float dmg  = rcp_approx(1.0f + e);
        float logit = fmaf(dmg, -10.0f, bond);

        float p = __expf(logit);   // logits bounded in (-10.7, 0.7): no max needed
        ssum += p;
        unsigned long long vv = *(const unsigned long long*)(&s_val[r * HS + 2 * lane]);
        ffma2(accv, dupf(p), vv);
    }

    float inv = __fdividef(1.0f, ssum);
    size_t ob = (size_t)(b * SEQ + t) * EMB + h * HS;
    float2 o = make_float2(accv.x * inv, accv.y * inv);
    *(float2*)(g_att + ob + 2 * lane) = o;
}

// ---------------- launch ----------------
extern "C" void kernel_launch(void* const* d_in, const int* in_sizes, int n_in,
                              void* d_out, int out_size)
{
    const float* x         = (const float*)d_in[0];
    const float* W_disp    = (const float*)d_in[1];
    const float* W_val     = (const float*)d_in[2];
    const float* rel       = (const float*)d_in[3];
    const float* W_strain  = (const float*)d_in[4];
    const float* W_pos     = (const float*)d_in[5];
    const float* W_bond    = (const float*)d_in[6];
    const float* W_dmg     = (const float*)d_in[7];
    const float* b_dmg     = (const float*)d_in[8];
    const float* W_dmg_out = (const float*)d_in[9];
    const float* b_dmg_out = (const float*)d_in[10];
    const float* W_cproj   = (const float*)d_in[11];
    float* out = (float*)d_out;

    float *disp_p, *val_p, *att_p;
    cudaGetSymbolAddress((void**)&disp_p, g_disp);
    cudaGetSymbolAddress((void**)&val_p,  g_val);
    cudaGetSymbolAddress((void**)&att_p,  g_att);

    const int M = BATCH * SEQ;   // 2048

    pos_kernel<<<1, 1024>>>(rel, W_pos);
    sgemm_kernel<<<dim3((NH * BD) / GBN, M / GBM), 256>>>(x, W_disp, disp_p, M, NH * BD, EMB);
    sgemm_kernel<<<dim3(EMB / GBN, M / GBM), 256>>>(x, W_val, val_p, M, EMB, EMB);
    fused_kernel<<<dim3(SEQ / TTILE, NH, BATCH), 512>>>(W_strain, W_dmg, b_dmg,
                                                        W_bond, W_dmg_out, b_dmg_out);
    sgemm_kernel<<<dim3(EMB / GBN, M / GBM), 256>>>(att_p, W_cproj, out, M, EMB, EMB);
}

// round 4
// speedup vs baseline: 1.8981x; 1.3724x over previous
#include <cuda_runtime.h>
#include <cuda_bf16.h>
#include <cstdint>
#include <math.h>

#define BATCH 2
#define SEQ   1024
#define EMB   1024
#define NH    16
#define HS    64
#define BD    16
#define DELTA 64
#define TTILE 16
#define NROWS (TTILE + DELTA - 1)   // 79

// ---------------- scratch (static device memory; no allocs) ----------------
__device__ float g_disp[BATCH * SEQ * NH * BD];
__device__ float g_val [BATCH * SEQ * EMB];
__device__ float g_att [BATCH * SEQ * EMB];
__device__ float g_pos [DELTA * BD];

// ---------------- helpers ----------------
__device__ __forceinline__ unsigned long long dupf(float v) {
    unsigned long long r;
    asm("mov.b64 %0, {%1, %1};" : "=l"(r) : "f"(v));
    return r;
}
__device__ __forceinline__ void ffma2(float2& d, unsigned long long a, unsigned long long b) {
    unsigned long long dd = *reinterpret_cast<unsigned long long*>(&d);
    asm("fma.rn.f32x2 %0, %1, %2, %0;" : "+l"(dd) : "l"(a), "l"(b));
    d = *reinterpret_cast<float2*>(&dd);
}
__device__ __forceinline__ float tanh_approx(float x) {
    float r; asm("tanh.approx.f32 %0, %1;" : "=f"(r) : "f"(x)); return r;
}
__device__ __forceinline__ float rcp_approx(float x) {
    float r; asm("rcp.approx.f32 %0, %1;" : "=f"(r) : "f"(x)); return r;
}

// split two floats into packed bf16x2 (hi) + packed bf16x2 residual (lo).
// low 16 bits of each u32 = first element (a), high = second (b).
__device__ __forceinline__ void split2(float a, float b, uint32_t& hi, uint32_t& lo) {
    __nv_bfloat162 h2 = __floats2bfloat162_rn(a, b);   // .x = a (low), .y = b (high)
    float ra = a - __bfloat162float(h2.x);
    float rb = b - __bfloat162float(h2.y);
    __nv_bfloat162 l2 = __floats2bfloat162_rn(ra, rb);
    hi = *reinterpret_cast<uint32_t*>(&h2);
    lo = *reinterpret_cast<uint32_t*>(&l2);
}

__device__ __forceinline__ void mma_bf16(float* c, const uint32_t* a, const uint32_t* b) {
    asm volatile(
        "mma.sync.aligned.m16n8k16.row.col.f32.bf16.bf16.f32 "
        "{%0,%1,%2,%3}, {%4,%5,%6,%7}, {%8,%9}, {%0,%1,%2,%3};"
        : "+f"(c[0]), "+f"(c[1]), "+f"(c[2]), "+f"(c[3])
        : "r"(a[0]), "r"(a[1]), "r"(a[2]), "r"(a[3]), "r"(b[0]), "r"(b[1]));
}

// ---------------- bf16-split HMMA GEMM ----------------
// C[2048, N] = A[2048, 1024] * B[1024, N], fp32 in/out, N in {256, 1024}.
// Block tile 128x128, 512 threads (16 warps, 32x32 each), K-chunk 32, dbl-buffered.
// smem rows padded to 80B: both A-frag and B-frag LDS.32 patterns conflict-free.
#define GEMM_K 1024
#define ROWB   80
#define ABLK   10240                 // 128 rows * 80B  (one pass, one buf)
#define SB_OFF 40960                 // after A (2 bufs x 2 passes)
#define GEMM_SMEM 81920

__device__ __forceinline__ void load_chunk(
    const float* __restrict__ A, const float* __restrict__ B,
    char* sm, int m0, int n0, int N, int s, int tid)
{
    const int buf = s & 1;
    const int k0 = s * 32;
    char* sa_hi = sm + buf * (2 * ABLK);
    char* sa_lo = sa_hi + ABLK;
    char* sb_hi = sm + SB_OFF + buf * (2 * ABLK);
    char* sb_lo = sb_hi + ABLK;

    // A: 128 rows x 32 k. thread -> row = tid>>2, two float4 segments.
    {
        const int row = tid >> 2;
        const float* ap = A + (size_t)(m0 + row) * GEMM_K + k0;
#pragma unroll
        for (int q = 0; q < 2; q++) {
            int c = (tid & 3) * 8 + q * 4;
            float4 v = *(const float4*)(ap + c);
            uint32_t h01, l01, h23, l23;
            split2(v.x, v.y, h01, l01);
            split2(v.z, v.w, h23, l23);
            uint32_t off = (uint32_t)(row * ROWB + c * 2);
            *(uint2*)(sa_hi + off) = make_uint2(h01, h23);
            *(uint2*)(sa_lo + off) = make_uint2(l01, l23);
        }
    }
    // B: 32 k-rows x 128 n. Stored k-transposed: sB[n][k]. thread -> one n, 8 k's.
    {
        const int nn = tid & 127;
        const int kb = (tid >> 7) * 8;
        const float* bp = B + (size_t)(k0 + kb) * N + n0 + nn;
        float v[8];
#pragma unroll
        for (int q = 0; q < 8; q++) v[q] = bp[(size_t)q * N];
        uint32_t base = (uint32_t)(nn * ROWB + kb * 2);
#pragma unroll
        for (int q = 0; q < 4; q++) {
            uint32_t hi, lo;
            split2(v[2 * q], v[2 * q + 1], hi, lo);
            *(uint32_t*)(sb_hi + base + q * 4) = hi;
            *(uint32_t*)(sb_lo + base + q * 4) = lo;
        }
    }
}

__global__ __launch_bounds__(512) void mma_gemm_kernel(
    const float* __restrict__ A, const float* __restrict__ B,
    float* __restrict__ C, int N)
{
    extern __shared__ __align__(16) char sm[];
    const int tid  = threadIdx.x;
    const int wid  = tid >> 5;
    const int lane = tid & 31;
    const int wm   = wid >> 2;        // 0..3  (rows wm*32)
    const int wn   = wid & 3;         // 0..3  (cols wn*32)
    const int m0 = blockIdx.y * 128;
    const int n0 = blockIdx.x * 128;
    const int r4 = lane >> 2;
    const int t  = lane & 3;

    float acc[2][4][4];
#pragma unroll
    for (int i = 0; i < 2; i++)
#pragma unroll
        for (int j = 0; j < 4; j++)
#pragma unroll
            for (int q = 0; q < 4; q++) acc[i][j][q] = 0.f;

    load_chunk(A, B, sm, m0, n0, N, 0, tid);
    __syncthreads();

    for (int s = 0; s < GEMM_K / 32; s++) {
        if (s + 1 < GEMM_K / 32)
            load_chunk(A, B, sm, m0, n0, N, s + 1, tid);

        const int buf = s & 1;
        const char* sa_hi = sm + buf * (2 * ABLK);
        const char* sa_lo = sa_hi + ABLK;
        const char* sb_hi = sm + SB_OFF + buf * (2 * ABLK);
        const char* sb_lo = sb_hi + ABLK;

#pragma unroll
        for (int kk = 0; kk < 2; kk++) {
            uint32_t Ah[2][4], Al[2][4], Bh[4][2], Bl[4][2];
#pragma unroll
            for (int i = 0; i < 2; i++) {
                uint32_t off = (uint32_t)((wm * 32 + i * 16 + r4) * ROWB + t * 4 + kk * 32);
                Ah[i][0] = *(const uint32_t*)(sa_hi + off);
                Ah[i][1] = *(const uint32_t*)(sa_hi + off + 8 * ROWB);
                Ah[i][2] = *(const uint32_t*)(sa_hi + off + 16);
                Ah[i][3] = *(const uint32_t*)(sa_hi + off + 8 * ROWB + 16);
                Al[i][0] = *(const uint32_t*)(sa_lo + off);
                Al[i][1] = *(const uint32_t*)(sa_lo + off + 8 * ROWB);
                Al[i][2] = *(const uint32_t*)(sa_lo + off + 16);
                Al[i][3] = *(const uint32_t*)(sa_lo + off + 8 * ROWB + 16);
            }
#pragma unroll
            for (int j = 0; j < 4; j++) {
                uint32_t off = (uint32_t)((wn * 32 + j * 8 + r4) * ROWB + t * 4 + kk * 32);
                Bh[j][0] = *(const uint32_t*)(sb_hi + off);
                Bh[j][1] = *(const uint32_t*)(sb_hi + off + 16);
                Bl[j][0] = *(const uint32_t*)(sb_lo + off);
                Bl[j][1] = *(const uint32_t*)(sb_lo + off + 16);
            }
#pragma unroll
            for (int i = 0; i < 2; i++)
#pragma unroll
                for (int j = 0; j < 4; j++) {
                    mma_bf16(acc[i][j], Ah[i], Bh[j]);
                    mma_bf16(acc[i][j], Ah[i], Bl[j]);
                    mma_bf16(acc[i][j], Al[i], Bh[j]);
                }
        }
        __syncthreads();
    }

    // epilogue
#pragma unroll
    for (int i = 0; i < 2; i++) {
        int row = m0 + wm * 32 + i * 16 + r4;
#pragma unroll
        for (int j = 0; j < 4; j++) {
            int col = n0 + wn * 32 + j * 8 + t * 2;
            *(float2*)(C + (size_t)row * N + col)       = make_float2(acc[i][j][0], acc[i][j][1]);
            *(float2*)(C + (size_t)(row + 8) * N + col) = make_float2(acc[i][j][2], acc[i][j][3]);
        }
    }
}

// ---------------- pos_term = rel_pos_emb @ W_pos  (64x16) ----------------
__global__ void pos_kernel(const float* __restrict__ rel, const float* __restrict__ Wp)
{
    int i = threadIdx.x;
    if (i < DELTA * BD) {
        int j = i >> 4, c = i & 15;
        float s = 0.f;
#pragma unroll
        for (int k = 0; k < BD; k++)
            s = fmaf(rel[j * BD + k], Wp[k * BD + c], s);
        g_pos[i] = s;
    }
}

// ---------------- fused window attention (unchanged, passing @109.8us) -----
__global__ __launch_bounds__(512) void fused_kernel(
    const float* __restrict__ W_strain, const float* __restrict__ W_dmg,
    const float* __restrict__ b_dmg,    const float* __restrict__ W_bond,
    const float* __restrict__ W_dmg_out, const float* __restrict__ b_dmg_out)
{
    __shared__ __align__(16) float s_val [NROWS * HS];
    __shared__ float s_disp[NROWS * BD];
    __shared__ float s_W   [BD * 32];
    __shared__ float s_P   [NROWS * 32];
    __shared__ float s_pos2[DELTA * 32];

    const int b  = blockIdx.z;
    const int h  = blockIdx.y;
    const int t0 = blockIdx.x * TTILE;
    const int tid = threadIdx.x;
    const int base_s = t0 - (DELTA - 1);

    for (int i = tid; i < NROWS * (HS / 4); i += 512) {
        int r  = i >> 4;
        int c4 = (i & 15) * 4;
        int s  = base_s + r;
        float4 v = make_float4(0.f, 0.f, 0.f, 0.f);
        if (s >= 0)
            v = *(const float4*)(g_val + (size_t)(b * SEQ + s) * EMB + h * HS + c4);
        *(float4*)(s_val + r * HS + c4) = v;
    }
    for (int i = tid; i < NROWS * (BD / 4); i += 512) {
        int r  = i >> 2;
        int c4 = (i & 3) * 4;
        int s  = base_s + r;
        float4 v = make_float4(0.f, 0.f, 0.f, 0.f);
        if (s >= 0)
            v = *(const float4*)(g_disp + (size_t)(b * SEQ + s) * (NH * BD) + h * BD + c4);
        *(float4*)(s_disp + r * BD + c4) = v;
    }
    if (tid < BD * 32) {
        int k = tid >> 5, c = tid & 31;
        s_W[tid] = (c < 16) ? W_strain[k * BD + c] : W_dmg[k * BD + (c - 16)];
    }
    for (int i = tid; i < DELTA * 32; i += 512) {
        int j = i >> 5, c = i & 31;
        s_pos2[i] = (c < 16) ? g_pos[j * BD + c] : b_dmg[c - 16];
    }
    __syncthreads();

    for (int i = tid; i < NROWS * 32; i += 512) {
        int r = i >> 5, c = i & 31;
        float s = 0.f;
#pragma unroll
        for (int k = 0; k < BD; k++)
            s = fmaf(s_disp[r * BD + k], s_W[k * 32 + c], s);
        s_P[i] = s;
    }
    __syncthreads();

    const int wid  = tid >> 5;
    const int lane = tid & 31;
    const int g    = lane >> 4;
    const int c    = lane & 15;
    const int t    = t0 + wid;

    const float wout = g ? W_dmg_out[c] : W_bond[c];
    const float bout = b_dmg_out[0];
    const float negpre = -s_P[(wid + (DELTA - 1)) * 32 + lane];

    int jstart = (DELTA - 1) - t;
    if (jstart < 0) jstart = 0;

    float ssum = 0.f;
    float2 accv = make_float2(0.f, 0.f);

#pragma unroll 2
    for (int j = jstart; j < DELTA; j++) {
        const int r = wid + j;
        float xx = s_P[r * 32 + lane] + s_pos2[j * 32 + lane] + negpre;
        float u    = xx * xx;
        float targ = xx * fmaf(u, 0.0356774081f, 0.7978845608f);
        float th   = tanh_approx(targ);
        float hx   = 0.5f * xx;
        float act  = fmaf(hx, th, hx);
        float v    = act * wout;
#pragma unroll
        for (int off = 1; off < 16; off <<= 1)
            v += __shfl_xor_sync(0xffffffffu, v, off);
        float other = __shfl_xor_sync(0xffffffffu, v, 16);
        float bond = g ? other : v;
        float dm   = g ? v : other;
        float e    = __expf(-dm - bout);
        float dmg  = rcp_approx(1.0f + e);
        float logit = fmaf(dmg, -10.0f, bond);

        float p = __expf(logit);
        ssum += p;
        unsigned long long vv = *(const unsigned long long*)(&s_val[r * HS + 2 * lane]);
        ffma2(accv, dupf(p), vv);
    }

    float inv = __fdividef(1.0f, ssum);
    size_t ob = (size_t)(b * SEQ + t) * EMB + h * HS;
    float2 o = make_float2(accv.x * inv, accv.y * inv);
    *(float2*)(g_att + ob + 2 * lane) = o;
}

// ---------------- launch ----------------
extern "C" void kernel_launch(void* const* d_in, const int* in_sizes, int n_in,
                              void* d_out, int out_size)
{
    const float* x         = (const float*)d_in[0];
    const float* W_disp    = (const float*)d_in[1];
    const float* W_val     = (const float*)d_in[2];
    const float* rel       = (const float*)d_in[3];
    const float* W_strain  = (const float*)d_in[4];
    const float* W_pos     = (const float*)d_in[5];
    const float* W_bond    = (const float*)d_in[6];
    const float* W_dmg     = (const float*)d_in[7];
    const float* b_dmg     = (const float*)d_in[8];
    const float* W_dmg_out = (const float*)d_in[9];
    const float* b_dmg_out = (const float*)d_in[10];
    const float* W_cproj   = (const float*)d_in[11];
    float* out = (float*)d_out;

    float *disp_p, *val_p, *att_p;
    cudaGetSymbolAddress((void**)&disp_p, g_disp);
    cudaGetSymbolAddress((void**)&val_p,  g_val);
    cudaGetSymbolAddress((void**)&att_p,  g_att);

    cudaFuncSetAttribute(mma_gemm_kernel,
                         cudaFuncAttributeMaxDynamicSharedMemorySize, GEMM_SMEM);

    const int M = BATCH * SEQ;   // 2048

    pos_kernel<<<1, 1024>>>(rel, W_pos);
    mma_gemm_kernel<<<dim3((NH * BD) / 128, M / 128), 512, GEMM_SMEM>>>(x, W_disp, disp_p, NH * BD);
    mma_gemm_kernel<<<dim3(EMB / 128, M / 128), 512, GEMM_SMEM>>>(x, W_val, val_p, EMB);
    fused_kernel<<<dim3(SEQ / TTILE, NH, BATCH), 512>>>(W_strain, W_dmg, b_dmg,
                                                        W_bond, W_dmg_out, b_dmg_out);
    mma_gemm_kernel<<<dim3(EMB / 128, M / 128), 512, GEMM_SMEM>>>(att_p, W_cproj, out, EMB);
}

// round 5
// speedup vs baseline: 2.5346x; 1.3353x over previous
#include <cuda_runtime.h>
#include <cuda_bf16.h>
#include <cstdint>
#include <math.h>

#define BATCH 2
#define SEQ   1024
#define EMB   1024
#define NH    16
#define HS    64
#define BD    16
#define DELTA 64
#define TTILE 16
#define NROWS (TTILE + DELTA - 1)   // 79
#define MTOT  (BATCH * SEQ)         // 2048

// ---------------- scratch (static device memory; no allocs) ----------------
__device__ float g_disp[MTOT * NH * BD];
__device__ float g_val [MTOT * EMB];
__device__ float g_pos [DELTA * BD];
__device__ __nv_bfloat16 g_xhi[MTOT * EMB], g_xlo[MTOT * EMB];
__device__ __nv_bfloat16 g_athi[MTOT * EMB], g_atlo[MTOT * EMB];
__device__ __nv_bfloat16 g_bthi[(NH * BD + EMB) * EMB], g_btlo[(NH * BD + EMB) * EMB]; // W_disp^T ++ W_val^T
__device__ __nv_bfloat16 g_cthi[EMB * EMB], g_ctlo[EMB * EMB];                          // W_cproj^T

// ---------------- scalar/packed helpers ----------------
typedef unsigned long long u64;

__device__ __forceinline__ u64 dupf(float v) {
    u64 r; asm("mov.b64 %0, {%1, %1};" : "=l"(r) : "f"(v)); return r;
}
__device__ __forceinline__ u64 pack2(float a, float b) {
    u64 r; asm("mov.b64 %0, {%1, %2};" : "=l"(r) : "f"(a), "f"(b)); return r;
}
__device__ __forceinline__ void unpack2(u64 v, float& a, float& b) {
    asm("mov.b64 {%0, %1}, %2;" : "=f"(a), "=f"(b) : "l"(v));
}
__device__ __forceinline__ u64 add2(u64 a, u64 b) {
    u64 r; asm("add.rn.f32x2 %0, %1, %2;" : "=l"(r) : "l"(a), "l"(b)); return r;
}
__device__ __forceinline__ u64 mul2(u64 a, u64 b) {
    u64 r; asm("mul.rn.f32x2 %0, %1, %2;" : "=l"(r) : "l"(a), "l"(b)); return r;
}
__device__ __forceinline__ u64 fma2(u64 a, u64 b, u64 c) {
    u64 r; asm("fma.rn.f32x2 %0, %1, %2, %3;" : "=l"(r) : "l"(a), "l"(b), "l"(c)); return r;
}
__device__ __forceinline__ float tanh_approx(float x) {
    float r; asm("tanh.approx.f32 %0, %1;" : "=f"(r) : "f"(x)); return r;
}
__device__ __forceinline__ float ex2(float x) {
    float r; asm("ex2.approx.f32 %0, %1;" : "=f"(r) : "f"(x)); return r;
}
__device__ __forceinline__ uint32_t smem_u32(const void* p) {
    uint32_t a;
    asm("{ .reg .u64 t; cvta.to.shared.u64 t, %1; cvt.u32.u64 %0, t; }" : "=r"(a) : "l"(p));
    return a;
}
__device__ __forceinline__ void cp16(uint32_t dst, const void* src) {
    asm volatile("{ .reg .u64 g; cvta.to.global.u64 g, %1; cp.async.cg.shared.global [%0], [g], 16; }"
                 :: "r"(dst), "l"(src) : "memory");
}
__device__ __forceinline__ void cp_commit() { asm volatile("cp.async.commit_group;" ::: "memory"); }
__device__ __forceinline__ void cp_wait(int pending) {
    if (pending) asm volatile("cp.async.wait_group 1;" ::: "memory");
    else         asm volatile("cp.async.wait_group 0;" ::: "memory");
}

// split two floats -> packed bf16x2 hi + packed bf16x2 residual
__device__ __forceinline__ void split2(float a, float b, uint32_t& hi, uint32_t& lo) {
    __nv_bfloat162 h2 = __floats2bfloat162_rn(a, b);
    float ra = a - __bfloat162float(h2.x);
    float rb = b - __bfloat162float(h2.y);
    __nv_bfloat162 l2 = __floats2bfloat162_rn(ra, rb);
    hi = *reinterpret_cast<uint32_t*>(&h2);
    lo = *reinterpret_cast<uint32_t*>(&l2);
}

__device__ __forceinline__ void mma_bf16(float* c, const uint32_t* a, const uint32_t* b) {
    asm volatile(
        "mma.sync.aligned.m16n8k16.row.col.f32.bf16.bf16.f32 "
        "{%0,%1,%2,%3}, {%4,%5,%6,%7}, {%8,%9}, {%0,%1,%2,%3};"
        : "+f"(c[0]), "+f"(c[1]), "+f"(c[2]), "+f"(c[3])
        : "r"(a[0]), "r"(a[1]), "r"(a[2]), "r"(a[3]), "r"(b[0]), "r"(b[1]));
}

// ---------------- conversion kernels ----------------
__global__ __launch_bounds__(512) void split_x_kernel(const float* __restrict__ x) {
    int i = blockIdx.x * 512 + threadIdx.x;          // over 1M float2
    float2 v = *(const float2*)(x + 2 * (size_t)i);
    uint32_t hi, lo;
    split2(v.x, v.y, hi, lo);
    *(uint32_t*)(&g_xhi[2 * (size_t)i]) = hi;
    *(uint32_t*)(&g_xlo[2 * (size_t)i]) = lo;
}

// transpose+split: out[n][k] = W[k][n];  src W is [K=1024][ldn]; dst rows width 1024.
__global__ void splitT_kernel(const float* __restrict__ W0, int ld0,
                              const float* __restrict__ W1, int ld1,
                              __nv_bfloat16* __restrict__ Dhi, __nv_bfloat16* __restrict__ Dlo)
{
    __shared__ float tile[32][33];
    const int k0 = blockIdx.y * 32;
    const int n0 = blockIdx.x * 32;
    const int tx = threadIdx.x, ty = threadIdx.y;   // 32 x 8
#pragma unroll
    for (int q = 0; q < 4; q++) {
        int k = k0 + ty + 8 * q;
        int n = n0 + tx;
        float v;
        if (n < ld0) v = W0[(size_t)k * ld0 + n];
        else         v = W1[(size_t)k * ld1 + (n - ld0)];
        tile[ty + 8 * q][tx] = v;
    }
    __syncthreads();
#pragma unroll
    for (int q = 0; q < 4; q++) {
        int n = n0 + ty + 8 * q;
        int k = k0 + tx;
        float v = tile[tx][ty + 8 * q];
        __nv_bfloat16 h = __float2bfloat16(v);
        Dhi[(size_t)n * EMB + k] = h;
        Dlo[(size_t)n * EMB + k] = __float2bfloat16(v - __bfloat162float(h));
    }
}

// ---------------- templated bf16-split HMMA GEMM ----------------
// C[M, ldc] tile (BM x BN) at (blockIdx.y*BM, blockIdx.x*BN)
// A split: [2048][1024] bf16 hi/lo; B split (pre-transposed): [n][1024] bf16 hi/lo.
#define ROWB 80
#define NSTG 32

template<int BM, int BN, int THREADS, int WN>
__global__ __launch_bounds__(THREADS) void gemm_kernel(
    const __nv_bfloat16* __restrict__ Ahi, const __nv_bfloat16* __restrict__ Alo,
    const __nv_bfloat16* __restrict__ Bhi, const __nv_bfloat16* __restrict__ Blo,
    float* __restrict__ C, int ldc)
{
    extern __shared__ __align__(16) char sm[];
    const uint32_t sbase = smem_u32(sm);
    const int tid  = threadIdx.x;
    const int wid  = tid >> 5;
    const int lane = tid & 31;
    const int wm   = wid / WN;
    const int wn   = wid % WN;
    const int m0 = blockIdx.y * BM;
    const int n0 = blockIdx.x * BN;
    const int r4 = lane >> 2;
    const int t  = lane & 3;

    const int BUFSZ = (BM + BN) * 2 * ROWB;

    float acc[2][4][4];
#pragma unroll
    for (int i = 0; i < 2; i++)
#pragma unroll
        for (int j = 0; j < 4; j++)
#pragma unroll
            for (int q = 0; q < 4; q++) acc[i][j][q] = 0.f;

    auto load_stage = [&](int s) {
        const int buf = s & 1;
        const int k0 = s * 32;
        uint32_t base = sbase + buf * BUFSZ;
#pragma unroll
        for (int i = tid; i < BM * 4; i += THREADS) {
            int row = i >> 2, seg = i & 3;
            uint32_t d = base + row * ROWB + seg * 16;
            const __nv_bfloat16* sa = Ahi + (size_t)(m0 + row) * EMB + k0 + seg * 8;
            cp16(d, sa);
            cp16(d + BM * ROWB, Alo + (size_t)(m0 + row) * EMB + k0 + seg * 8);
        }
#pragma unroll
        for (int i = tid; i < BN * 4; i += THREADS) {
            int row = i >> 2, seg = i & 3;
            uint32_t d = base + 2 * BM * ROWB + row * ROWB + seg * 16;
            cp16(d, Bhi + (size_t)(n0 + row) * EMB + k0 + seg * 8);
            cp16(d + BN * ROWB, Blo + (size_t)(n0 + row) * EMB + k0 + seg * 8);
        }
        cp_commit();
    };

    load_stage(0);

    for (int s = 0; s < NSTG; s++) {
        if (s + 1 < NSTG) { load_stage(s + 1); cp_wait(1); }
        else              cp_wait(0);
        __syncthreads();

        const int buf = s & 1;
        const char* sa_hi = sm + buf * BUFSZ;
        const char* sa_lo = sa_hi + BM * ROWB;
        const char* sb_hi = sm + buf * BUFSZ + 2 * BM * ROWB;
        const char* sb_lo = sb_hi + BN * ROWB;

#pragma unroll
        for (int kk = 0; kk < 2; kk++) {
            uint32_t Ah[2][4], Al[2][4], Bh[4][2], Bl[4][2];
#pragma unroll
            for (int i = 0; i < 2; i++) {
                uint32_t off = (uint32_t)((wm * 32 + i * 16 + r4) * ROWB + t * 4 + kk * 32);
                Ah[i][0] = *(const uint32_t*)(sa_hi + off);
                Ah[i][1] = *(const uint32_t*)(sa_hi + off + 8 * ROWB);
                Ah[i][2] = *(const uint32_t*)(sa_hi + off + 16);
                Ah[i][3] = *(const uint32_t*)(sa_hi + off + 8 * ROWB + 16);
                Al[i][0] = *(const uint32_t*)(sa_lo + off);
                Al[i][1] = *(const uint32_t*)(sa_lo + off + 8 * ROWB);
                Al[i][2] = *(const uint32_t*)(sa_lo + off + 16);
                Al[i][3] = *(const uint32_t*)(sa_lo + off + 8 * ROWB + 16);
            }
#pragma unroll
            for (int j = 0; j < 4; j++) {
                uint32_t off = (uint32_t)((wn * 32 + j * 8 + r4) * ROWB + t * 4 + kk * 32);
                Bh[j][0] = *(const uint32_t*)(sb_hi + off);
                Bh[j][1] = *(const uint32_t*)(sb_hi + off + 16);
                Bl[j][0] = *(const uint32_t*)(sb_lo + off);
                Bl[j][1] = *(const uint32_t*)(sb_lo + off + 16);
            }
#pragma unroll
            for (int i = 0; i < 2; i++)
#pragma unroll
                for (int j = 0; j < 4; j++) {
                    mma_bf16(acc[i][j], Ah[i], Bh[j]);
                    mma_bf16(acc[i][j], Ah[i], Bl[j]);
                    mma_bf16(acc[i][j], Al[i], Bh[j]);
                }
        }
        __syncthreads();
    }

#pragma unroll
    for (int i = 0; i < 2; i++) {
        int row = m0 + wm * 32 + i * 16 + r4;
#pragma unroll
        for (int j = 0; j < 4; j++) {
            int col = n0 + wn * 32 + j * 8 + t * 2;
            *(float2*)(C + (size_t)row * ldc + col)       = make_float2(acc[i][j][0], acc[i][j][1]);
            *(float2*)(C + (size_t)(row + 8) * ldc + col) = make_float2(acc[i][j][2], acc[i][j][3]);
        }
    }
}

// ---------------- pos_term = rel_pos_emb @ W_pos  (64x16) ----------------
__global__ void pos_kernel(const float* __restrict__ rel, const float* __restrict__ Wp)
{
    int i = threadIdx.x;
    if (i < DELTA * BD) {
        int j = i >> 4, c = i & 15;
        float s = 0.f;
#pragma unroll
        for (int k = 0; k < BD; k++)
            s = fmaf(rel[j * BD + k], Wp[k * BD + c], s);
        g_pos[i] = s;
    }
}

// ---------------- fused window attention (f32x2, 2 j per pass) ----------------
__global__ __launch_bounds__(512) void fused_kernel(
    const float* __restrict__ W_strain, const float* __restrict__ W_dmg,
    const float* __restrict__ b_dmg,    const float* __restrict__ W_bond,
    const float* __restrict__ W_dmg_out, const float* __restrict__ b_dmg_out)
{
    __shared__ __align__(16) float s_val [NROWS * HS];   // 20.2 KB
    __shared__ float  s_disp[NROWS * BD];                // 5.1 KB
    __shared__ float2 s_W2  [BD * 16];                   // 2 KB   (strain, dmg) per (k,c)
    __shared__ float2 s_P2  [NROWS * 16];                // 10.1 KB (bond dot, dmg dot)
    __shared__ float2 s_pp2 [DELTA * 16];                // 8 KB   (pos, b_dmg)

    const int b  = blockIdx.z;
    const int h  = blockIdx.y;
    const int t0 = blockIdx.x * TTILE;
    const int tid = threadIdx.x;
    const int base_s = t0 - (DELTA - 1);

    for (int i = tid; i < NROWS * (HS / 4); i += 512) {
        int r  = i >> 4;
        int c4 = (i & 15) * 4;
        int s  = base_s + r;
        float4 v = make_float4(0.f, 0.f, 0.f, 0.f);
        if (s >= 0)
            v = *(const float4*)(g_val + (size_t)(b * SEQ + s) * EMB + h * HS + c4);
        *(float4*)(s_val + r * HS + c4) = v;
    }
    for (int i = tid; i < NROWS * (BD / 4); i += 512) {
        int r  = i >> 2;
        int c4 = (i & 3) * 4;
        int s  = base_s + r;
        float4 v = make_float4(0.f, 0.f, 0.f, 0.f);
        if (s >= 0)
            v = *(const float4*)(g_disp + (size_t)(b * SEQ + s) * (NH * BD) + h * BD + c4);
        *(float4*)(s_disp + r * BD + c4) = v;
    }
    if (tid < BD * 16)
        s_W2[tid] = make_float2(W_strain[tid], W_dmg[tid]);
    for (int i = tid; i < DELTA * 16; i += 512)
        s_pp2[i] = make_float2(g_pos[i], b_dmg[i & 15]);
    __syncthreads();

    // stage B: packed dots  P2[r][c] = (disp_r . Ws_c, disp_r . Wd_c)
    for (int i = tid; i < NROWS * 16; i += 512) {
        int r = i >> 4, c = i & 15;
        u64 acc = 0;
#pragma unroll
        for (int k = 0; k < BD; k++)
            acc = fma2(dupf(s_disp[r * BD + k]), *(const u64*)(&s_W2[k * 16 + c]), acc);
        *(u64*)(&s_P2[i]) = acc;
    }
    __syncthreads();

    const int wid  = tid >> 5;
    const int lane = tid & 31;
    const int half = lane >> 4;
    const int c    = lane & 15;
    const int t    = t0 + wid;

    const u64 wout2 = pack2(0.5f * W_bond[c], 0.5f * W_dmg_out[c]);
    const float c0  = 0.5f * b_dmg_out[0];
    const float L2E = 1.44269504089f, N5L2E = -7.21347520444f;
    const u64 C0v = dupf(0.7978845608f), C1v = dupf(0.0356774081f);

    float2 npf = s_P2[(wid + DELTA - 1) * 16 + c];
    const u64 negpre = pack2(-npf.x, -npf.y);

    const bool masked = (t < DELTA - 1);
    const int jstart = (DELTA - 1) - t;

    float ssum = 0.f;
    u64 acc0 = 0, acc1 = 0;

    for (int jj = 0; jj < 32; jj++) {
        const int j = 2 * jj + half;
        const int r = wid + j;
        u64 P  = *(const u64*)(&s_P2[r * 16 + c]);
        u64 pp = *(const u64*)(&s_pp2[j * 16 + c]);
        u64 xx = add2(add2(P, pp), negpre);
        // gelu (tanh form), 0.5 folded into wout2
        u64 u2   = mul2(xx, xx);
        u64 t1   = fma2(u2, C1v, C0v);
        u64 targ = mul2(xx, t1);
        float ta, tb; unpack2(targ, ta, tb);
        u64 th = pack2(tanh_approx(ta), tanh_approx(tb));
        u64 m  = fma2(th, xx, xx);          // xx*(1+th)
        u64 w  = mul2(m, wout2);
        float bond, dm; unpack2(w, bond, dm);
#pragma unroll
        for (int off = 1; off < 16; off <<= 1) {
            bond += __shfl_xor_sync(0xffffffffu, bond, off);
            dm   += __shfl_xor_sync(0xffffffffu, dm, off);
        }
        // sigmoid via tanh; p = exp(bond - 10*sigmoid) = exp(lt - 5)
        float hh  = fmaf(dm, 0.5f, c0);
        float th2 = tanh_approx(hh);
        float lt  = fmaf(th2, -5.f, bond);
        float p   = ex2(fmaf(lt, L2E, N5L2E));
        if (masked && j < jstart) p = 0.f;
        ssum += p;
        u64 pd = dupf(p);
        acc0 = fma2(pd, *(const u64*)(&s_val[r * HS + 2 * c]),      acc0);
        acc1 = fma2(pd, *(const u64*)(&s_val[r * HS + 32 + 2 * c]), acc1);
    }

    // combine the two j-halves
    float a0x, a0y, a1x, a1y;
    unpack2(acc0, a0x, a0y);
    unpack2(acc1, a1x, a1y);
    a0x += __shfl_xor_sync(0xffffffffu, a0x, 16);
    a0y += __shfl_xor_sync(0xffffffffu, a0y, 16);
    a1x += __shfl_xor_sync(0xffffffffu, a1x, 16);
    a1y += __shfl_xor_sync(0xffffffffu, a1y, 16);
    ssum += __shfl_xor_sync(0xffffffffu, ssum, 16);

    if (half == 0) {
        float inv = __fdividef(1.0f, ssum);
        size_t ob = (size_t)(b * SEQ + t) * EMB + h * HS;
        uint32_t hi, lo;
        split2(a0x * inv, a0y * inv, hi, lo);
        *(uint32_t*)(&g_athi[ob + 2 * c]) = hi;
        *(uint32_t*)(&g_atlo[ob + 2 * c]) = lo;
        split2(a1x * inv, a1y * inv, hi, lo);
        *(uint32_t*)(&g_athi[ob + 32 + 2 * c]) = hi;
        *(uint32_t*)(&g_atlo[ob + 32 + 2 * c]) = lo;
    }
}

// ---------------- launch ----------------
extern "C" void kernel_launch(void* const* d_in, const int* in_sizes, int n_in,
                              void* d_out, int out_size)
{
    const float* x         = (const float*)d_in[0];
    const float* W_disp    = (const float*)d_in[1];
    const float* W_val     = (const float*)d_in[2];
    const float* rel       = (const float*)d_in[3];
    const float* W_strain  = (const float*)d_in[4];
    const float* W_pos     = (const float*)d_in[5];
    const float* W_bond    = (const float*)d_in[6];
    const float* W_dmg     = (const float*)d_in[7];
    const float* b_dmg     = (const float*)d_in[8];
    const float* W_dmg_out = (const float*)d_in[9];
    const float* b_dmg_out = (const float*)d_in[10];
    const float* W_cproj   = (const float*)d_in[11];
    float* out = (float*)d_out;

    float *disp_p, *val_p;
    __nv_bfloat16 *xhi, *xlo, *athi, *atlo, *bthi, *btlo, *cthi, *ctlo;
    cudaGetSymbolAddress((void**)&disp_p, g_disp);
    cudaGetSymbolAddress((void**)&val_p,  g_val);
    cudaGetSymbolAddress((void**)&xhi, g_xhi);   cudaGetSymbolAddress((void**)&xlo, g_xlo);
    cudaGetSymbolAddress((void**)&athi, g_athi); cudaGetSymbolAddress((void**)&atlo, g_atlo);
    cudaGetSymbolAddress((void**)&bthi, g_bthi); cudaGetSymbolAddress((void**)&btlo, g_btlo);
    cudaGetSymbolAddress((void**)&cthi, g_cthi); cudaGetSymbolAddress((void**)&ctlo, g_ctlo);

    const int SMEM_BIG   = (128 + 128) * 2 * ROWB * 2;   // 81920
    const int SMEM_SMALL = (64 + 64) * 2 * ROWB * 2;     // 40960
    cudaFuncSetAttribute((const void*)gemm_kernel<128, 128, 512, 4>,
                         cudaFuncAttributeMaxDynamicSharedMemorySize, SMEM_BIG);
    cudaFuncSetAttribute((const void*)gemm_kernel<64, 64, 128, 2>,
                         cudaFuncAttributeMaxDynamicSharedMemorySize, SMEM_SMALL);

    pos_kernel<<<1, 1024>>>(rel, W_pos);
    split_x_kernel<<<(MTOT * EMB / 2) / 512, 512>>>(x);
    splitT_kernel<<<dim3((NH * BD + EMB) / 32, EMB / 32), dim3(32, 8)>>>(
        W_disp, NH * BD, W_val, EMB, bthi, btlo);
    splitT_kernel<<<dim3(EMB / 32, EMB / 32), dim3(32, 8)>>>(
        W_cproj, EMB, W_cproj, EMB, cthi, ctlo);

    gemm_kernel<64, 64, 128, 2><<<dim3((NH * BD) / 64, MTOT / 64), 128, SMEM_SMALL>>>(
        xhi, xlo, bthi, btlo, disp_p, NH * BD);
    gemm_kernel<128, 128, 512, 4><<<dim3(EMB / 128, MTOT / 128), 512, SMEM_BIG>>>(
        xhi, xlo, bthi + (size_t)(NH * BD) * EMB, btlo + (size_t)(NH * BD) * EMB, val_p, EMB);
    fused_kernel<<<dim3(SEQ / TTILE, NH, BATCH), 512>>>(W_strain, W_dmg, b_dmg,
                                                        W_bond, W_dmg_out, b_dmg_out);
    gemm_kernel<128, 128, 512, 4><<<dim3(EMB / 128, MTOT / 128), 512, SMEM_BIG>>>(
        athi, atlo, cthi, ctlo, out, EMB);
}

// round 6
// speedup vs baseline: 3.0728x; 1.2123x over previous
#include <cuda_runtime.h>
#include <cuda_fp16.h>
#include <cstdint>
#include <math.h>

#define BATCH 2
#define SEQ   1024
#define EMB   1024
#define NH    16
#define HS    64
#define BD    16
#define DELTA 64
#define TTILE 16
#define NROWS (TTILE + DELTA - 1)   // 79
#define MTOT  (BATCH * SEQ)         // 2048

// ---------------- scratch (static device memory; no allocs) ----------------
__device__ float g_disp[MTOT * NH * BD];
__device__ float g_val [MTOT * EMB];
__device__ float g_pos [DELTA * BD];
__device__ __half g_xhi[MTOT * EMB], g_xlo[MTOT * EMB];
__device__ __half g_athi[MTOT * EMB], g_atlo[MTOT * EMB];
__device__ __half g_bthi[(NH * BD + EMB) * EMB];   // [W_disp^T ++ W_val^T], hi only
__device__ __half g_cthi[EMB * EMB];               // W_cproj^T, hi only

// ---------------- scalar/packed helpers ----------------
typedef unsigned long long u64;

__device__ __forceinline__ u64 dupf(float v) {
    u64 r; asm("mov.b64 %0, {%1, %1};" : "=l"(r) : "f"(v)); return r;
}
__device__ __forceinline__ u64 pack2(float a, float b) {
    u64 r; asm("mov.b64 %0, {%1, %2};" : "=l"(r) : "f"(a), "f"(b)); return r;
}
__device__ __forceinline__ void unpack2(u64 v, float& a, float& b) {
    asm("mov.b64 {%0, %1}, %2;" : "=f"(a), "=f"(b) : "l"(v));
}
__device__ __forceinline__ u64 add2(u64 a, u64 b) {
    u64 r; asm("add.rn.f32x2 %0, %1, %2;" : "=l"(r) : "l"(a), "l"(b)); return r;
}
__device__ __forceinline__ u64 mul2(u64 a, u64 b) {
    u64 r; asm("mul.rn.f32x2 %0, %1, %2;" : "=l"(r) : "l"(a), "l"(b)); return r;
}
__device__ __forceinline__ u64 fma2(u64 a, u64 b, u64 c) {
    u64 r; asm("fma.rn.f32x2 %0, %1, %2, %3;" : "=l"(r) : "l"(a), "l"(b), "l"(c)); return r;
}
__device__ __forceinline__ float tanh_approx(float x) {
    float r; asm("tanh.approx.f32 %0, %1;" : "=f"(r) : "f"(x)); return r;
}
__device__ __forceinline__ float ex2(float x) {
    float r; asm("ex2.approx.f32 %0, %1;" : "=f"(r) : "f"(x)); return r;
}
__device__ __forceinline__ uint32_t smem_u32(const void* p) {
    uint32_t a;
    asm("{ .reg .u64 t; cvta.to.shared.u64 t, %1; cvt.u32.u64 %0, t; }" : "=r"(a) : "l"(p));
    return a;
}
__device__ __forceinline__ void cp16(uint32_t dst, const void* src) {
    asm volatile("{ .reg .u64 g; cvta.to.global.u64 g, %1; cp.async.cg.shared.global [%0], [g], 16; }"
                 :: "r"(dst), "l"(src) : "memory");
}
__device__ __forceinline__ void cp_commit() { asm volatile("cp.async.commit_group;" ::: "memory"); }
__device__ __forceinline__ void cp_wait(int pending) {
    if (pending) asm volatile("cp.async.wait_group 1;" ::: "memory");
    else         asm volatile("cp.async.wait_group 0;" ::: "memory");
}

// split two floats -> packed fp16x2 hi + packed fp16x2 residual
__device__ __forceinline__ void split2h(float a, float b, uint32_t& hi, uint32_t& lo) {
    __half2 h2 = __floats2half2_rn(a, b);
    float ra = a - __half2float(h2.x);
    float rb = b - __half2float(h2.y);
    __half2 l2 = __floats2half2_rn(ra, rb);
    hi = *reinterpret_cast<uint32_t*>(&h2);
    lo = *reinterpret_cast<uint32_t*>(&l2);
}

__device__ __forceinline__ void mma_fp16(float* c, const uint32_t* a, const uint32_t* b) {
    asm volatile(
        "mma.sync.aligned.m16n8k16.row.col.f32.f16.f16.f32 "
        "{%0,%1,%2,%3}, {%4,%5,%6,%7}, {%8,%9}, {%0,%1,%2,%3};"
        : "+f"(c[0]), "+f"(c[1]), "+f"(c[2]), "+f"(c[3])
        : "r"(a[0]), "r"(a[1]), "r"(a[2]), "r"(a[3]), "r"(b[0]), "r"(b[1]));
}

// ---------------- conversion kernels ----------------
__global__ __launch_bounds__(512) void split_x_kernel(const float* __restrict__ x) {
    int i = blockIdx.x * 512 + threadIdx.x;          // over 1M float2
    float2 v = *(const float2*)(x + 2 * (size_t)i);
    uint32_t hi, lo;
    split2h(v.x, v.y, hi, lo);
    *(uint32_t*)(&g_xhi[2 * (size_t)i]) = hi;
    *(uint32_t*)(&g_xlo[2 * (size_t)i]) = lo;
}

// transpose + fp16 hi-only: out[n][k] = W[k][n]
__global__ void splitT_kernel(const float* __restrict__ W0, int ld0,
                              const float* __restrict__ W1, int ld1,
                              __half* __restrict__ Dhi)
{
    __shared__ float tile[32][33];
    const int k0 = blockIdx.y * 32;
    const int n0 = blockIdx.x * 32;
    const int tx = threadIdx.x, ty = threadIdx.y;   // 32 x 8
#pragma unroll
    for (int q = 0; q < 4; q++) {
        int k = k0 + ty + 8 * q;
        int n = n0 + tx;
        float v;
        if (n < ld0) v = W0[(size_t)k * ld0 + n];
        else         v = W1[(size_t)k * ld1 + (n - ld0)];
        tile[ty + 8 * q][tx] = v;
    }
    __syncthreads();
#pragma unroll
    for (int q = 0; q < 4; q++) {
        int n = n0 + ty + 8 * q;
        int k = k0 + tx;
        Dhi[(size_t)n * EMB + k] = __float2half_rn(tile[tx][ty + 8 * q]);
    }
}

// ---------------- fp16 2-pass split HMMA GEMM ----------------
// C = A * B^T; A split hi/lo fp16 [M][1024], B hi-only fp16 [n][1024] (pre-transposed).
// C += Ah*Bh + Al*Bh  (B residual dropped: ~7e-5 rel)
#define ROWB 80
#define NSTG 32

template<int BM, int BN, int THREADS, int WN>
__global__ __launch_bounds__(THREADS) void gemm_kernel(
    const __half* __restrict__ Ahi, const __half* __restrict__ Alo,
    const __half* __restrict__ Bhi,
    float* __restrict__ C, int ldc)
{
    extern __shared__ __align__(16) char sm[];
    const uint32_t sbase = smem_u32(sm);
    const int tid  = threadIdx.x;
    const int wid  = tid >> 5;
    const int lane = tid & 31;
    const int wm   = wid / WN;
    const int wn   = wid % WN;
    const int m0 = blockIdx.y * BM;
    const int n0 = blockIdx.x * BN;
    const int r4 = lane >> 2;
    const int t  = lane & 3;

    const int BUFSZ = (2 * BM + BN) * ROWB;

    float acc[2][4][4];
#pragma unroll
    for (int i = 0; i < 2; i++)
#pragma unroll
        for (int j = 0; j < 4; j++)
#pragma unroll
            for (int q = 0; q < 4; q++) acc[i][j][q] = 0.f;

    auto load_stage = [&](int s) {
        const int buf = s & 1;
        const int k0 = s * 32;
        uint32_t base = sbase + buf * BUFSZ;
#pragma unroll
        for (int i = tid; i < BM * 4; i += THREADS) {
            int row = i >> 2, seg = i & 3;
            uint32_t d = base + row * ROWB + seg * 16;
            cp16(d, Ahi + (size_t)(m0 + row) * EMB + k0 + seg * 8);
            cp16(d + BM * ROWB, Alo + (size_t)(m0 + row) * EMB + k0 + seg * 8);
        }
#pragma unroll
        for (int i = tid; i < BN * 4; i += THREADS) {
            int row = i >> 2, seg = i & 3;
            cp16(base + 2 * BM * ROWB + row * ROWB + seg * 16,
                 Bhi + (size_t)(n0 + row) * EMB + k0 + seg * 8);
        }
        cp_commit();
    };

    load_stage(0);

    for (int s = 0; s < NSTG; s++) {
        if (s + 1 < NSTG) { load_stage(s + 1); cp_wait(1); }
        else              cp_wait(0);
        __syncthreads();

        const int buf = s & 1;
        const char* sa_hi = sm + buf * BUFSZ;
        const char* sa_lo = sa_hi + BM * ROWB;
        const char* sb_hi = sm + buf * BUFSZ + 2 * BM * ROWB;

#pragma unroll
        for (int kk = 0; kk < 2; kk++) {
            uint32_t Ah[2][4], Al[2][4], Bh[4][2];
#pragma unroll
            for (int i = 0; i < 2; i++) {
                uint32_t off = (uint32_t)((wm * 32 + i * 16 + r4) * ROWB + t * 4 + kk * 32);
                Ah[i][0] = *(const uint32_t*)(sa_hi + off);
                Ah[i][1] = *(const uint32_t*)(sa_hi + off + 8 * ROWB);
                Ah[i][2] = *(const uint32_t*)(sa_hi + off + 16);
                Ah[i][3] = *(const uint32_t*)(sa_hi + off + 8 * ROWB + 16);
                Al[i][0] = *(const uint32_t*)(sa_lo + off);
                Al[i][1] = *(const uint32_t*)(sa_lo + off + 8 * ROWB);
                Al[i][2] = *(const uint32_t*)(sa_lo + off + 16);
                Al[i][3] = *(const uint32_t*)(sa_lo + off + 8 * ROWB + 16);
            }
#pragma unroll
            for (int j = 0; j < 4; j++) {
                uint32_t off = (uint32_t)((wn * 32 + j * 8 + r4) * ROWB + t * 4 + kk * 32);
                Bh[j][0] = *(const uint32_t*)(sb_hi + off);
                Bh[j][1] = *(const uint32_t*)(sb_hi + off + 16);
            }
#pragma unroll
            for (int i = 0; i < 2; i++)
#pragma unroll
                for (int j = 0; j < 4; j++) {
                    mma_fp16(acc[i][j], Ah[i], Bh[j]);
                    mma_fp16(acc[i][j], Al[i], Bh[j]);
                }
        }
        __syncthreads();
    }

#pragma unroll
    for (int i = 0; i < 2; i++) {
        int row = m0 + wm * 32 + i * 16 + r4;
#pragma unroll
        for (int j = 0; j < 4; j++) {
            int col = n0 + wn * 32 + j * 8 + t * 2;
            *(float2*)(C + (size_t)row * ldc + col)       = make_float2(acc[i][j][0], acc[i][j][1]);
            *(float2*)(C + (size_t)(row + 8) * ldc + col) = make_float2(acc[i][j][2], acc[i][j][3]);
        }
    }
}

// ---------------- pos_term = rel_pos_emb @ W_pos  (64x16) ----------------
__global__ void pos_kernel(const float* __restrict__ rel, const float* __restrict__ Wp)
{
    int i = threadIdx.x;
    if (i < DELTA * BD) {
        int j = i >> 4, c = i & 15;
        float s = 0.f;
#pragma unroll
        for (int k = 0; k < BD; k++)
            s = fmaf(rel[j * BD + k], Wp[k * BD + c], s);
        g_pos[i] = s;
    }
}

// ---------------- fused window attention (f32x2, 2 j per pass) ----------------
__global__ __launch_bounds__(512) void fused_kernel(
    const float* __restrict__ W_strain, const float* __restrict__ W_dmg,
    const float* __restrict__ b_dmg,    const float* __restrict__ W_bond,
    const float* __restrict__ W_dmg_out, const float* __restrict__ b_dmg_out)
{
    __shared__ __align__(16) float s_val [NROWS * HS];
    __shared__ float  s_disp[NROWS * BD];
    __shared__ float2 s_W2  [BD * 16];
    __shared__ float2 s_P2  [NROWS * 16];
    __shared__ float2 s_pp2 [DELTA * 16];

    const int b  = blockIdx.z;
    const int h  = blockIdx.y;
    const int t0 = blockIdx.x * TTILE;
    const int tid = threadIdx.x;
    const int base_s = t0 - (DELTA - 1);

    for (int i = tid; i < NROWS * (HS / 4); i += 512) {
        int r  = i >> 4;
        int c4 = (i & 15) * 4;
        int s  = base_s + r;
        float4 v = make_float4(0.f, 0.f, 0.f, 0.f);
        if (s >= 0)
            v = *(const float4*)(g_val + (size_t)(b * SEQ + s) * EMB + h * HS + c4);
        *(float4*)(s_val + r * HS + c4) = v;
    }
    for (int i = tid; i < NROWS * (BD / 4); i += 512) {
        int r  = i >> 2;
        int c4 = (i & 3) * 4;
        int s  = base_s + r;
        float4 v = make_float4(0.f, 0.f, 0.f, 0.f);
        if (s >= 0)
            v = *(const float4*)(g_disp + (size_t)(b * SEQ + s) * (NH * BD) + h * BD + c4);
        *(float4*)(s_disp + r * BD + c4) = v;
    }
    if (tid < BD * 16)
        s_W2[tid] = make_float2(W_strain[tid], W_dmg[tid]);
    for (int i = tid; i < DELTA * 16; i += 512)
        s_pp2[i] = make_float2(g_pos[i], b_dmg[i & 15]);
    __syncthreads();

    for (int i = tid; i < NROWS * 16; i += 512) {
        int r = i >> 4, c = i & 15;
        u64 acc = 0;
#pragma unroll
        for (int k = 0; k < BD; k++)
            acc = fma2(dupf(s_disp[r * BD + k]), *(const u64*)(&s_W2[k * 16 + c]), acc);
        *(u64*)(&s_P2[i]) = acc;
    }
    __syncthreads();

    const int wid  = tid >> 5;
    const int lane = tid & 31;
    const int half = lane >> 4;
    const int c    = lane & 15;
    const int t    = t0 + wid;

    const u64 wout2 = pack2(0.5f * W_bond[c], 0.5f * W_dmg_out[c]);
    const float c0  = 0.5f * b_dmg_out[0];
    const float L2E = 1.44269504089f, N5L2E = -7.21347520444f;
    const u64 C0v = dupf(0.7978845608f), C1v = dupf(0.0356774081f);

    float2 npf = s_P2[(wid + DELTA - 1) * 16 + c];
    const u64 negpre = pack2(-npf.x, -npf.y);

    const bool masked = (t < DELTA - 1);
    const int jstart = (DELTA - 1) - t;

    float ssum = 0.f;
    u64 acc0 = 0, acc1 = 0;

    for (int jj = 0; jj < 32; jj++) {
        const int j = 2 * jj + half;
        const int r = wid + j;
        u64 P  = *(const u64*)(&s_P2[r * 16 + c]);
        u64 pp = *(const u64*)(&s_pp2[j * 16 + c]);
        u64 xx = add2(add2(P, pp), negpre);
        u64 u2   = mul2(xx, xx);
        u64 t1   = fma2(u2, C1v, C0v);
        u64 targ = mul2(xx, t1);
        float ta, tb; unpack2(targ, ta, tb);
        u64 th = pack2(tanh_approx(ta), tanh_approx(tb));
        u64 m  = fma2(th, xx, xx);
        u64 w  = mul2(m, wout2);
        float bond, dm; unpack2(w, bond, dm);
#pragma unroll
        for (int off = 1; off < 16; off <<= 1) {
            bond += __shfl_xor_sync(0xffffffffu, bond, off);
            dm   += __shfl_xor_sync(0xffffffffu, dm, off);
        }
        float hh  = fmaf(dm, 0.5f, c0);
        float th2 = tanh_approx(hh);
        float lt  = fmaf(th2, -5.f, bond);
        float p   = ex2(fmaf(lt, L2E, N5L2E));
        if (masked && j < jstart) p = 0.f;
        ssum += p;
        u64 pd = dupf(p);
        acc0 = fma2(pd, *(const u64*)(&s_val[r * HS + 2 * c]),      acc0);
        acc1 = fma2(pd, *(const u64*)(&s_val[r * HS + 32 + 2 * c]), acc1);
    }

    float a0x, a0y, a1x, a1y;
    unpack2(acc0, a0x, a0y);
    unpack2(acc1, a1x, a1y);
    a0x += __shfl_xor_sync(0xffffffffu, a0x, 16);
    a0y += __shfl_xor_sync(0xffffffffu, a0y, 16);
    a1x += __shfl_xor_sync(0xffffffffu, a1x, 16);
    a1y += __shfl_xor_sync(0xffffffffu, a1y, 16);
    ssum += __shfl_xor_sync(0xffffffffu, ssum, 16);

    if (half == 0) {
        float inv = __fdividef(1.0f, ssum);
        size_t ob = (size_t)(b * SEQ + t) * EMB + h * HS;
        uint32_t hi, lo;
        split2h(a0x * inv, a0y * inv, hi, lo);
        *(uint32_t*)(&g_athi[ob + 2 * c]) = hi;
        *(uint32_t*)(&g_atlo[ob + 2 * c]) = lo;
        split2h(a1x * inv, a1y * inv, hi, lo);
        *(uint32_t*)(&g_athi[ob + 32 + 2 * c]) = hi;
        *(uint32_t*)(&g_atlo[ob + 32 + 2 * c]) = lo;
    }
}

// ---------------- launch ----------------
extern "C" void kernel_launch(void* const* d_in, const int* in_sizes, int n_in,
                              void* d_out, int out_size)
{
    const float* x         = (const float*)d_in[0];
    const float* W_disp    = (const float*)d_in[1];
    const float* W_val     = (const float*)d_in[2];
    const float* rel       = (const float*)d_in[3];
    const float* W_strain  = (const float*)d_in[4];
    const float* W_pos     = (const float*)d_in[5];
    const float* W_bond    = (const float*)d_in[6];
    const float* W_dmg     = (const float*)d_in[7];
    const float* b_dmg     = (const float*)d_in[8];
    const float* W_dmg_out = (const float*)d_in[9];
    const float* b_dmg_out = (const float*)d_in[10];
    const float* W_cproj   = (const float*)d_in[11];
    float* out = (float*)d_out;

    float *disp_p, *val_p;
    __half *xhi, *xlo, *athi, *atlo, *bthi, *cthi;
    cudaGetSymbolAddress((void**)&disp_p, g_disp);
    cudaGetSymbolAddress((void**)&val_p,  g_val);
    cudaGetSymbolAddress((void**)&xhi, g_xhi);   cudaGetSymbolAddress((void**)&xlo, g_xlo);
    cudaGetSymbolAddress((void**)&athi, g_athi); cudaGetSymbolAddress((void**)&atlo, g_atlo);
    cudaGetSymbolAddress((void**)&bthi, g_bthi); cudaGetSymbolAddress((void**)&cthi, g_cthi);

    const int SMEM_BIG   = (2 * 128 + 128) * ROWB * 2;   // 61440
    const int SMEM_SMALL = (2 * 64 + 64) * ROWB * 2;     // 30720
    cudaFuncSetAttribute((const void*)gemm_kernel<128, 128, 512, 4>,
                         cudaFuncAttributeMaxDynamicSharedMemorySize, SMEM_BIG);
    cudaFuncSetAttribute((const void*)gemm_kernel<64, 64, 128, 2>,
                         cudaFuncAttributeMaxDynamicSharedMemorySize, SMEM_SMALL);

    pos_kernel<<<1, 1024>>>(rel, W_pos);
    split_x_kernel<<<(MTOT * EMB / 2) / 512, 512>>>(x);
    splitT_kernel<<<dim3((NH * BD + EMB) / 32, EMB / 32), dim3(32, 8)>>>(
        W_disp, NH * BD, W_val, EMB, bthi);
    splitT_kernel<<<dim3(EMB / 32, EMB / 32), dim3(32, 8)>>>(
        W_cproj, EMB, W_cproj, EMB, cthi);

    gemm_kernel<64, 64, 128, 2><<<dim3((NH * BD) / 64, MTOT / 64), 128, SMEM_SMALL>>>(
        xhi, xlo, bthi, disp_p, NH * BD);
    gemm_kernel<128, 128, 512, 4><<<dim3(EMB / 128, MTOT / 128), 512, SMEM_BIG>>>(
        xhi, xlo, bthi + (size_t)(NH * BD) * EMB, val_p, EMB);
    fused_kernel<<<dim3(SEQ / TTILE, NH, BATCH), 512>>>(W_strain, W_dmg, b_dmg,
                                                        W_bond, W_dmg_out, b_dmg_out);
    gemm_kernel<128, 128, 512, 4><<<dim3(EMB / 128, MTOT / 128), 512, SMEM_BIG>>>(
        athi, atlo, cthi, out, EMB);
}

// round 7
// speedup vs baseline: 3.3408x; 1.0872x over previous
#include <cuda_runtime.h>
#include <cuda_fp16.h>
#include <cstdint>
#include <math.h>

#define BATCH 2
#define SEQ   1024
#define EMB   1024
#define NH    16
#define HS    64
#define BD    16
#define DELTA 64
#define TTILE 16
#define NROWS (TTILE + DELTA - 1)   // 79
#define MTOT  (BATCH * SEQ)         // 2048

// ---------------- scratch (static device memory; no allocs) ----------------
__device__ float g_disp[MTOT * NH * BD];
__device__ float g_val [MTOT * EMB];
__device__ float g_pos [DELTA * BD];
__device__ __half g_xhi[MTOT * EMB], g_xlo[MTOT * EMB];
__device__ __half g_athi[MTOT * EMB], g_atlo[MTOT * EMB];
__device__ __half g_bthi[(NH * BD + EMB) * EMB];   // [W_disp^T ++ W_val^T], hi only
__device__ __half g_cthi[EMB * EMB];               // W_cproj^T, hi only

// ---------------- scalar/packed helpers ----------------
typedef unsigned long long u64;

__device__ __forceinline__ u64 dupf(float v) {
    u64 r; asm("mov.b64 %0, {%1, %1};" : "=l"(r) : "f"(v)); return r;
}
__device__ __forceinline__ u64 pack2(float a, float b) {
    u64 r; asm("mov.b64 %0, {%1, %2};" : "=l"(r) : "f"(a), "f"(b)); return r;
}
__device__ __forceinline__ void unpack2(u64 v, float& a, float& b) {
    asm("mov.b64 {%0, %1}, %2;" : "=f"(a), "=f"(b) : "l"(v));
}
__device__ __forceinline__ u64 add2(u64 a, u64 b) {
    u64 r; asm("add.rn.f32x2 %0, %1, %2;" : "=l"(r) : "l"(a), "l"(b)); return r;
}
__device__ __forceinline__ u64 mul2(u64 a, u64 b) {
    u64 r; asm("mul.rn.f32x2 %0, %1, %2;" : "=l"(r) : "l"(a), "l"(b)); return r;
}
__device__ __forceinline__ u64 fma2(u64 a, u64 b, u64 c) {
    u64 r; asm("fma.rn.f32x2 %0, %1, %2, %3;" : "=l"(r) : "l"(a), "l"(b), "l"(c)); return r;
}
__device__ __forceinline__ float tanh_approx(float x) {
    float r; asm("tanh.approx.f32 %0, %1;" : "=f"(r) : "f"(x)); return r;
}
__device__ __forceinline__ float ex2(float x) {
    float r; asm("ex2.approx.f32 %0, %1;" : "=f"(r) : "f"(x)); return r;
}
__device__ __forceinline__ uint32_t smem_u32(const void* p) {
    uint32_t a;
    asm("{ .reg .u64 t; cvta.to.shared.u64 t, %1; cvt.u32.u64 %0, t; }" : "=r"(a) : "l"(p));
    return a;
}
__device__ __forceinline__ void cp16(uint32_t dst, const void* src) {
    asm volatile("{ .reg .u64 g; cvta.to.global.u64 g, %1; cp.async.cg.shared.global [%0], [g], 16; }"
                 :: "r"(dst), "l"(src) : "memory");
}
__device__ __forceinline__ void cp_commit() { asm volatile("cp.async.commit_group;" ::: "memory"); }
__device__ __forceinline__ void cp_wait(int pending) {
    if (pending) asm volatile("cp.async.wait_group 1;" ::: "memory");
    else         asm volatile("cp.async.wait_group 0;" ::: "memory");
}

// split two floats -> packed fp16x2 hi + packed fp16x2 residual
__device__ __forceinline__ void split2h(float a, float b, uint32_t& hi, uint32_t& lo) {
    __half2 h2 = __floats2half2_rn(a, b);
    float ra = a - __half2float(h2.x);
    float rb = b - __half2float(h2.y);
    __half2 l2 = __floats2half2_rn(ra, rb);
    hi = *reinterpret_cast<uint32_t*>(&h2);
    lo = *reinterpret_cast<uint32_t*>(&l2);
}

__device__ __forceinline__ void mma_fp16(float* c, const uint32_t* a, const uint32_t* b) {
    asm volatile(
        "mma.sync.aligned.m16n8k16.row.col.f32.f16.f16.f32 "
        "{%0,%1,%2,%3}, {%4,%5,%6,%7}, {%8,%9}, {%0,%1,%2,%3};"
        : "+f"(c[0]), "+f"(c[1]), "+f"(c[2]), "+f"(c[3])
        : "r"(a[0]), "r"(a[1]), "r"(a[2]), "r"(a[3]), "r"(b[0]), "r"(b[1]));
}

// ---------------- conversion kernels ----------------
__global__ __launch_bounds__(512) void split_x_kernel(const float* __restrict__ x) {
    int i = blockIdx.x * 512 + threadIdx.x;          // over 1M float2
    float2 v = *(const float2*)(x + 2 * (size_t)i);
    uint32_t hi, lo;
    split2h(v.x, v.y, hi, lo);
    *(uint32_t*)(&g_xhi[2 * (size_t)i]) = hi;
    *(uint32_t*)(&g_xlo[2 * (size_t)i]) = lo;
}

// transpose + fp16 hi-only: out[n][k] = W[k][n]
__global__ void splitT_kernel(const float* __restrict__ W0, int ld0,
                              const float* __restrict__ W1, int ld1,
                              __half* __restrict__ Dhi)
{
    __shared__ float tile[32][33];
    const int k0 = blockIdx.y * 32;
    const int n0 = blockIdx.x * 32;
    const int tx = threadIdx.x, ty = threadIdx.y;   // 32 x 8
#pragma unroll
    for (int q = 0; q < 4; q++) {
        int k = k0 + ty + 8 * q;
        int n = n0 + tx;
        float v;
        if (n < ld0) v = W0[(size_t)k * ld0 + n];
        else         v = W1[(size_t)k * ld1 + (n - ld0)];
        tile[ty + 8 * q][tx] = v;
    }
    __syncthreads();
#pragma unroll
    for (int q = 0; q < 4; q++) {
        int n = n0 + ty + 8 * q;
        int k = k0 + tx;
        Dhi[(size_t)n * EMB + k] = __float2half_rn(tile[tx][ty + 8 * q]);
    }
}

// ---------------- fp16 2-pass split HMMA GEMM (unchanged) ----------------
#define ROWB 80
#define NSTG 32

template<int BM, int BN, int THREADS, int WN>
__global__ __launch_bounds__(THREADS) void gemm_kernel(
    const __half* __restrict__ Ahi, const __half* __restrict__ Alo,
    const __half* __restrict__ Bhi,
    float* __restrict__ C, int ldc)
{
    extern __shared__ __align__(16) char sm[];
    const uint32_t sbase = smem_u32(sm);
    const int tid  = threadIdx.x;
    const int wid  = tid >> 5;
    const int lane = tid & 31;
    const int wm   = wid / WN;
    const int wn   = wid % WN;
    const int m0 = blockIdx.y * BM;
    const int n0 = blockIdx.x * BN;
    const int r4 = lane >> 2;
    const int t  = lane & 3;

    const int BUFSZ = (2 * BM + BN) * ROWB;

    float acc[2][4][4];
#pragma unroll
    for (int i = 0; i < 2; i++)
#pragma unroll
        for (int j = 0; j < 4; j++)
#pragma unroll
            for (int q = 0; q < 4; q++) acc[i][j][q] = 0.f;

    auto load_stage = [&](int s) {
        const int buf = s & 1;
        const int k0 = s * 32;
        uint32_t base = sbase + buf * BUFSZ;
#pragma unroll
        for (int i = tid; i < BM * 4; i += THREADS) {
            int row = i >> 2, seg = i & 3;
            uint32_t d = base + row * ROWB + seg * 16;
            cp16(d, Ahi + (size_t)(m0 + row) * EMB + k0 + seg * 8);
            cp16(d + BM * ROWB, Alo + (size_t)(m0 + row) * EMB + k0 + seg * 8);
        }
#pragma unroll
        for (int i = tid; i < BN * 4; i += THREADS) {
            int row = i >> 2, seg = i & 3;
            cp16(base + 2 * BM * ROWB + row * ROWB + seg * 16,
                 Bhi + (size_t)(n0 + row) * EMB + k0 + seg * 8);
        }
        cp_commit();
    };

    load_stage(0);

    for (int s = 0; s < NSTG; s++) {
        if (s + 1 < NSTG) { load_stage(s + 1); cp_wait(1); }
        else              cp_wait(0);
        __syncthreads();

        const int buf = s & 1;
        const char* sa_hi = sm + buf * BUFSZ;
        const char* sa_lo = sa_hi + BM * ROWB;
        const char* sb_hi = sm + buf * BUFSZ + 2 * BM * ROWB;

#pragma unroll
        for (int kk = 0; kk < 2; kk++) {
            uint32_t Ah[2][4], Al[2][4], Bh[4][2];
#pragma unroll
            for (int i = 0; i < 2; i++) {
                uint32_t off = (uint32_t)((wm * 32 + i * 16 + r4) * ROWB + t * 4 + kk * 32);
                Ah[i][0] = *(const uint32_t*)(sa_hi + off);
                Ah[i][1] = *(const uint32_t*)(sa_hi + off + 8 * ROWB);
                Ah[i][2] = *(const uint32_t*)(sa_hi + off + 16);
                Ah[i][3] = *(const uint32_t*)(sa_hi + off + 8 * ROWB + 16);
                Al[i][0] = *(const uint32_t*)(sa_lo + off);
                Al[i][1] = *(const uint32_t*)(sa_lo + off + 8 * ROWB);
                Al[i][2] = *(const uint32_t*)(sa_lo + off + 16);
                Al[i][3] = *(const uint32_t*)(sa_lo + off + 8 * ROWB + 16);
            }
#pragma unroll
            for (int j = 0; j < 4; j++) {
                uint32_t off = (uint32_t)((wn * 32 + j * 8 + r4) * ROWB + t * 4 + kk * 32);
                Bh[j][0] = *(const uint32_t*)(sb_hi + off);
                Bh[j][1] = *(const uint32_t*)(sb_hi + off + 16);
            }
#pragma unroll
            for (int i = 0; i < 2; i++)
#pragma unroll
                for (int j = 0; j < 4; j++) {
                    mma_fp16(acc[i][j], Ah[i], Bh[j]);
                    mma_fp16(acc[i][j], Al[i], Bh[j]);
                }
        }
        __syncthreads();
    }

#pragma unroll
    for (int i = 0; i < 2; i++) {
        int row = m0 + wm * 32 + i * 16 + r4;
#pragma unroll
        for (int j = 0; j < 4; j++) {
            int col = n0 + wn * 32 + j * 8 + t * 2;
            *(float2*)(C + (size_t)row * ldc + col)       = make_float2(acc[i][j][0], acc[i][j][1]);
            *(float2*)(C + (size_t)(row + 8) * ldc + col) = make_float2(acc[i][j][2], acc[i][j][3]);
        }
    }
}

// ---------------- pos_term = rel_pos_emb @ W_pos  (64x16) ----------------
__global__ void pos_kernel(const float* __restrict__ rel, const float* __restrict__ Wp)
{
    int i = threadIdx.x;
    if (i < DELTA * BD) {
        int j = i >> 4, c = i & 15;
        float s = 0.f;
#pragma unroll
        for (int k = 0; k < BD; k++)
            s = fmaf(rel[j * BD + k], Wp[k * BD + c], s);
        g_pos[i] = s;
    }
}

// ---------------- fused window attention: lanes = j layout ----------------
__global__ __launch_bounds__(512) void fused_kernel(
    const float* __restrict__ W_strain, const float* __restrict__ W_dmg,
    const float* __restrict__ b_dmg,    const float* __restrict__ W_bond,
    const float* __restrict__ W_dmg_out, const float* __restrict__ b_dmg_out)
{
    __shared__ __align__(16) float s_val [NROWS * HS];   // 20.2 KB
    __shared__ float  s_disp[NROWS * BD];                // 5.1 KB
    __shared__ float2 s_W2  [BD * 16];                   // 2 KB  (strain, dmg)[k][c]
    __shared__ float2 s_PT  [16 * NROWS];                // 10.1 KB  [c][r]
    __shared__ float2 s_ppT [16 * DELTA];                // 8 KB     [c][j] (pos, b_dmg)
    __shared__ float2 s_wout[16];                        // (0.5*Wb, 0.5*Wdo)

    const int b  = blockIdx.z;
    const int h  = blockIdx.y;
    const int t0 = blockIdx.x * TTILE;
    const int tid = threadIdx.x;
    const int base_s = t0 - (DELTA - 1);

    // ---- phase 0: loads ----
    for (int i = tid; i < NROWS * (HS / 4); i += 512) {
        int r  = i >> 4;
        int c4 = (i & 15) * 4;
        int s  = base_s + r;
        float4 v = make_float4(0.f, 0.f, 0.f, 0.f);
        if (s >= 0)
            v = *(const float4*)(g_val + (size_t)(b * SEQ + s) * EMB + h * HS + c4);
        *(float4*)(s_val + r * HS + c4) = v;
    }
    for (int i = tid; i < NROWS * (BD / 4); i += 512) {
        int r  = i >> 2;
        int c4 = (i & 3) * 4;
        int s  = base_s + r;
        float4 v = make_float4(0.f, 0.f, 0.f, 0.f);
        if (s >= 0)
            v = *(const float4*)(g_disp + (size_t)(b * SEQ + s) * (NH * BD) + h * BD + c4);
        *(float4*)(s_disp + r * BD + c4) = v;
    }
    if (tid < BD * 16)
        s_W2[tid] = make_float2(W_strain[tid], W_dmg[tid]);
    if (tid < 16)
        s_wout[tid] = make_float2(0.5f * W_bond[tid], 0.5f * W_dmg_out[tid]);
    for (int i = tid; i < 16 * DELTA; i += 512) {
        int c = i >> 6, j = i & 63;
        s_ppT[i] = make_float2(g_pos[j * BD + c], b_dmg[c]);
    }
    __syncthreads();

    // ---- phase 1: PT[c][r] = (disp_r . Ws_c, disp_r . Wd_c) ----
    for (int i = tid; i < NROWS * 16; i += 512) {
        int r = i >> 4, c = i & 15;
        u64 acc = 0;
#pragma unroll
        for (int k = 0; k < BD; k++)
            acc = fma2(dupf(s_disp[r * BD + k]), *(const u64*)(&s_W2[k * 16 + c]), acc);
        *(u64*)(&s_PT[c * NROWS + r]) = acc;
    }
    __syncthreads();

    // ---- phase 2: logits for all j (lane = j, two halves) ----
    const int wid  = tid >> 5;
    const int lane = tid & 31;
    const int t    = t0 + wid;
    const int j0   = lane;
    const int j1   = lane + 32;

    const u64 NEG1 = dupf(-1.f);
    const u64 C0v = dupf(0.7978845608f), C1v = dupf(0.0356774081f);
    const float c0  = 0.5f * b_dmg_out[0];
    const float L2E = 1.44269504089f, N5L2E = -7.21347520444f;

    u64 accA = 0, accB = 0;   // packed (bond, dmg) sums for j0, j1

#pragma unroll
    for (int c = 0; c < 16; c++) {
        const u64* Pc  = (const u64*)(&s_PT[c * NROWS + wid]);
        const u64* ppc = (const u64*)(&s_ppT[c * DELTA]);
        u64 pre = Pc[DELTA - 1];                 // broadcast: P[c][wid+63]
        u64 w2  = *(const u64*)(&s_wout[c]);

        {
            u64 s  = add2(Pc[j0], ppc[j0]);
            u64 xx = fma2(pre, NEG1, s);
            u64 u2 = mul2(xx, xx);
            u64 t1 = fma2(u2, C1v, C0v);
            u64 tg = mul2(xx, t1);
            float ta, tb; unpack2(tg, ta, tb);
            u64 th = pack2(tanh_approx(ta), tanh_approx(tb));
            u64 m  = fma2(th, xx, xx);
            accA = fma2(m, w2, accA);
        }
        {
            u64 s  = add2(Pc[j1], ppc[j1]);
            u64 xx = fma2(pre, NEG1, s);
            u64 u2 = mul2(xx, xx);
            u64 t1 = fma2(u2, C1v, C0v);
            u64 tg = mul2(xx, t1);
            float ta, tb; unpack2(tg, ta, tb);
            u64 th = pack2(tanh_approx(ta), tanh_approx(tb));
            u64 m  = fma2(th, xx, xx);
            accB = fma2(m, w2, accB);
        }
    }

    const int jstart = (t < DELTA - 1) ? (DELTA - 1 - t) : 0;

    float p0, p1;
    {
        float bond, dm; unpack2(accA, bond, dm);
        float th2 = tanh_approx(fmaf(dm, 0.5f, c0));
        float lt  = fmaf(th2, -5.f, bond);
        p0 = ex2(fmaf(lt, L2E, N5L2E));
        if (j0 < jstart) p0 = 0.f;
    }
    {
        float bond, dm; unpack2(accB, bond, dm);
        float th2 = tanh_approx(fmaf(dm, 0.5f, c0));
        float lt  = fmaf(th2, -5.f, bond);
        p1 = ex2(fmaf(lt, L2E, N5L2E));
        if (j1 < jstart) p1 = 0.f;
    }

    // ---- phase 3: weighted val sum; lane = channel pair ----
    float ssum = p0 + p1;
    u64 acc = 0;
    const float* vbase = s_val + wid * HS + 2 * lane;
#pragma unroll 8
    for (int j = 0; j < 32; j++) {
        float pj = __shfl_sync(0xffffffffu, p0, j);
        acc = fma2(dupf(pj), *(const u64*)(vbase + j * HS), acc);
    }
#pragma unroll 8
    for (int j = 0; j < 32; j++) {
        float pj = __shfl_sync(0xffffffffu, p1, j);
        acc = fma2(dupf(pj), *(const u64*)(vbase + (j + 32) * HS), acc);
    }

#pragma unroll
    for (int off = 1; off < 32; off <<= 1)
        ssum += __shfl_xor_sync(0xffffffffu, ssum, off);

    float ax, ay; unpack2(acc, ax, ay);
    float inv = __fdividef(1.0f, ssum);
    size_t ob = (size_t)(b * SEQ + t) * EMB + h * HS;
    uint32_t hi, lo;
    split2h(ax * inv, ay * inv, hi, lo);
    *(uint32_t*)(&g_athi[ob + 2 * lane]) = hi;
    *(uint32_t*)(&g_atlo[ob + 2 * lane]) = lo;
}

// ---------------- launch ----------------
extern "C" void kernel_launch(void* const* d_in, const int* in_sizes, int n_in,
                              void* d_out, int out_size)
{
    const float* x         = (const float*)d_in[0];
    const float* W_disp    = (const float*)d_in[1];
    const float* W_val     = (const float*)d_in[2];
    const float* rel       = (const float*)d_in[3];
    const float* W_strain  = (const float*)d_in[4];
    const float* W_pos     = (const float*)d_in[5];
    const float* W_bond    = (const float*)d_in[6];
    const float* W_dmg     = (const float*)d_in[7];
    const float* b_dmg     = (const float*)d_in[8];
    const float* W_dmg_out = (const float*)d_in[9];
    const float* b_dmg_out = (const float*)d_in[10];
    const float* W_cproj   = (const float*)d_in[11];
    float* out = (float*)d_out;

    float *disp_p, *val_p;
    __half *xhi, *xlo, *athi, *atlo, *bthi, *cthi;
    cudaGetSymbolAddress((void**)&disp_p, g_disp);
    cudaGetSymbolAddress((void**)&val_p,  g_val);
    cudaGetSymbolAddress((void**)&xhi, g_xhi);   cudaGetSymbolAddress((void**)&xlo, g_xlo);
    cudaGetSymbolAddress((void**)&athi, g_athi); cudaGetSymbolAddress((void**)&atlo, g_atlo);
    cudaGetSymbolAddress((void**)&bthi, g_bthi); cudaGetSymbolAddress((void**)&cthi, g_cthi);

    const int SMEM_BIG   = (2 * 128 + 128) * ROWB * 2;   // 61440
    const int SMEM_SMALL = (2 * 64 + 64) * ROWB * 2;     // 30720
    cudaFuncSetAttribute((const void*)gemm_kernel<128, 128, 512, 4>,
                         cudaFuncAttributeMaxDynamicSharedMemorySize, SMEM_BIG);
    cudaFuncSetAttribute((const void*)gemm_kernel<64, 64, 128, 2>,
                         cudaFuncAttributeMaxDynamicSharedMemorySize, SMEM_SMALL);

    pos_kernel<<<1, 1024>>>(rel, W_pos);
    split_x_kernel<<<(MTOT * EMB / 2) / 512, 512>>>(x);
    splitT_kernel<<<dim3((NH * BD + EMB) / 32, EMB / 32), dim3(32, 8)>>>(
        W_disp, NH * BD, W_val, EMB, bthi);
    splitT_kernel<<<dim3(EMB / 32, EMB / 32), dim3(32, 8)>>>(
        W_cproj, EMB, W_cproj, EMB, cthi);

    gemm_kernel<64, 64, 128, 2><<<dim3((NH * BD) / 64, MTOT / 64), 128, SMEM_SMALL>>>(
        xhi, xlo, bthi, disp_p, NH * BD);
    gemm_kernel<128, 128, 512, 4><<<dim3(EMB / 128, MTOT / 128), 512, SMEM_BIG>>>(
        xhi, xlo, bthi + (size_t)(NH * BD) * EMB, val_p, EMB);
    fused_kernel<<<dim3(SEQ / TTILE, NH, BATCH), 512>>>(W_strain, W_dmg, b_dmg,
                                                        W_bond, W_dmg_out, b_dmg_out);
    gemm_kernel<128, 128, 512, 4><<<dim3(EMB / 128, MTOT / 128), 512, SMEM_BIG>>>(
        athi, atlo, cthi, out, EMB);
}

// round 10
// speedup vs baseline: 3.7599x; 1.1255x over previous
#include <cuda_runtime.h>
#include <cuda_fp16.h>
#include <cstdint>
#include <math.h>

#define BATCH 2
#define SEQ   1024
#define EMB   1024
#define NH    16
#define HS    64
#define BD    16
#define DELTA 64
#define TTILE 16
#define NROWS (TTILE + DELTA - 1)   // 79
#define MTOT  (BATCH * SEQ)         // 2048

// ---------------- scratch (static device memory; no allocs) ----------------
__device__ float g_disp[MTOT * NH * BD];
__device__ float g_val [MTOT * EMB];
__device__ float g_pos [DELTA * BD];
__device__ __half g_xhi[MTOT * EMB], g_xlo[MTOT * EMB];
__device__ __half g_athi[MTOT * EMB], g_atlo[MTOT * EMB];
__device__ __half g_bthi[(NH * BD + EMB) * EMB];   // [W_disp^T ++ W_val^T], hi only
__device__ __half g_cthi[EMB * EMB];               // W_cproj^T, hi only

// ---------------- helpers (pd_ prefix: no vendor-header collisions) --------
typedef unsigned long long u64;

__device__ __forceinline__ u64 pd_dupf(float v) {
    u64 r; asm("mov.b64 %0, {%1, %1};" : "=l"(r) : "f"(v)); return r;
}
__device__ __forceinline__ void pd_unpack2(u64 v, float& a, float& b) {
    asm("mov.b64 {%0, %1}, %2;" : "=f"(a), "=f"(b) : "l"(v));
}
__device__ __forceinline__ u64 pd_fma2(u64 a, u64 b, u64 c) {
    u64 r; asm("fma.rn.f32x2 %0, %1, %2, %3;" : "=l"(r) : "l"(a), "l"(b), "l"(c)); return r;
}
__device__ __forceinline__ float pd_tanhf(float x) {
    float r; asm("tanh.approx.f32 %0, %1;" : "=f"(r) : "f"(x)); return r;
}
__device__ __forceinline__ __half2 pd_tanh2(__half2 x) {
    uint32_t xi = *reinterpret_cast<uint32_t*>(&x), ri;
    asm("tanh.approx.f16x2 %0, %1;" : "=r"(ri) : "r"(xi));
    return *reinterpret_cast<__half2*>(&ri);
}
__device__ __forceinline__ float pd_ex2(float x) {
    float r; asm("ex2.approx.f32 %0, %1;" : "=f"(r) : "f"(x)); return r;
}
__device__ __forceinline__ uint32_t pd_smem_u32(const void* p) {
    uint32_t a;
    asm("{ .reg .u64 t; cvta.to.shared.u64 t, %1; cvt.u32.u64 %0, t; }" : "=r"(a) : "l"(p));
    return a;
}
__device__ __forceinline__ void pd_cp16(uint32_t dst, const void* src) {
    asm volatile("{ .reg .u64 g; cvta.to.global.u64 g, %1; cp.async.cg.shared.global [%0], [g], 16; }"
                 :: "r"(dst), "l"(src) : "memory");
}
__device__ __forceinline__ void pd_cp_commit() { asm volatile("cp.async.commit_group;" ::: "memory"); }
__device__ __forceinline__ void pd_cp_wait(int pending) {
    if (pending) asm volatile("cp.async.wait_group 1;" ::: "memory");
    else         asm volatile("cp.async.wait_group 0;" ::: "memory");
}

__device__ __forceinline__ void pd_split2h(float a, float b, uint32_t& hi, uint32_t& lo) {
    __half2 h2 = __floats2half2_rn(a, b);
    float ra = a - __half2float(h2.x);
    float rb = b - __half2float(h2.y);
    __half2 l2 = __floats2half2_rn(ra, rb);
    hi = *reinterpret_cast<uint32_t*>(&h2);
    lo = *reinterpret_cast<uint32_t*>(&l2);
}

__device__ __forceinline__ void pd_mma_fp16(float* c, const uint32_t* a, const uint32_t* b) {
    asm volatile(
        "mma.sync.aligned.m16n8k16.row.col.f32.f16.f16.f32 "
        "{%0,%1,%2,%3}, {%4,%5,%6,%7}, {%8,%9}, {%0,%1,%2,%3};"
        : "+f"(c[0]), "+f"(c[1]), "+f"(c[2]), "+f"(c[3])
        : "r"(a[0]), "r"(a[1]), "r"(a[2]), "r"(a[3]), "r"(b[0]), "r"(b[1]));
}

#define PD_LDSM_X4(r, a) \
    asm volatile("ldmatrix.sync.aligned.m8n8.x4.shared.b16 {%0,%1,%2,%3}, [%4];" \
                 : "=r"((r)[0]), "=r"((r)[1]), "=r"((r)[2]), "=r"((r)[3]) : "r"(a))
#define PD_LDSM_X2T(r, a) \
    asm volatile("ldmatrix.sync.aligned.m8n8.x2.trans.shared.b16 {%0,%1}, [%2];" \
                 : "=r"((r)[0]), "=r"((r)[1]) : "r"(a))

// ---------------- conversion kernels ----------------
__global__ __launch_bounds__(512) void split_x_kernel(const float* __restrict__ x) {
    int i = blockIdx.x * 512 + threadIdx.x;
    float2 v = *(const float2*)(x + 2 * (size_t)i);
    uint32_t hi, lo;
    pd_split2h(v.x, v.y, hi, lo);
    *(uint32_t*)(&g_xhi[2 * (size_t)i]) = hi;
    *(uint32_t*)(&g_xlo[2 * (size_t)i]) = lo;
}

__global__ void splitT_kernel(const float* __restrict__ W0, int ld0,
                              const float* __restrict__ W1, int ld1,
                              __half* __restrict__ Dhi)
{
    __shared__ float tile[32][33];
    const int k0 = blockIdx.y * 32;
    const int n0 = blockIdx.x * 32;
    const int tx = threadIdx.x, ty = threadIdx.y;
#pragma unroll
    for (int q = 0; q < 4; q++) {
        int k = k0 + ty + 8 * q;
        int n = n0 + tx;
        float v;
        if (n < ld0) v = W0[(size_t)k * ld0 + n];
        else         v = W1[(size_t)k * ld1 + (n - ld0)];
        tile[ty + 8 * q][tx] = v;
    }
    __syncthreads();
#pragma unroll
    for (int q = 0; q < 4; q++) {
        int n = n0 + ty + 8 * q;
        int k = k0 + tx;
        Dhi[(size_t)n * EMB + k] = __float2half_rn(tile[tx][ty + 8 * q]);
    }
}

// ---------------- fp16 split HMMA GEMM (LO: include A-residual pass) -------
#define ROWB 80
#define NSTG 32

template<int BM, int BN, int THREADS, int WN, bool LO>
__global__ __launch_bounds__(THREADS) void gemm_kernel(
    const __half* __restrict__ Ahi, const __half* __restrict__ Alo,
    const __half* __restrict__ Bhi,
    float* __restrict__ C, int ldc)
{
    extern __shared__ __align__(16) char sm[];
    const uint32_t sbase = pd_smem_u32(sm);
    const int tid  = threadIdx.x;
    const int wid  = tid >> 5;
    const int lane = tid & 31;
    const int wm   = wid / WN;
    const int wn   = wid % WN;
    const int m0 = blockIdx.y * BM;
    const int n0 = blockIdx.x * BN;
    const int r4 = lane >> 2;
    const int t  = lane & 3;

    const int NA = LO ? 2 : 1;
    const int BUFSZ = (NA * BM + BN) * ROWB;

    float acc[2][4][4];
#pragma unroll
    for (int i = 0; i < 2; i++)
#pragma unroll
        for (int j = 0; j < 4; j++)
#pragma unroll
            for (int q = 0; q < 4; q++) acc[i][j][q] = 0.f;

    auto load_stage = [&](int s) {
        const int buf = s & 1;
        const int k0 = s * 32;
        uint32_t base = sbase + buf * BUFSZ;
#pragma unroll
        for (int i = tid; i < BM * 4; i += THREADS) {
            int row = i >> 2, seg = i & 3;
            uint32_t d = base + row * ROWB + seg * 16;
            pd_cp16(d, Ahi + (size_t)(m0 + row) * EMB + k0 + seg * 8);
            if (LO)
                pd_cp16(d + BM * ROWB, Alo + (size_t)(m0 + row) * EMB + k0 + seg * 8);
        }
#pragma unroll
        for (int i = tid; i < BN * 4; i += THREADS) {
            int row = i >> 2, seg = i & 3;
            pd_cp16(base + NA * BM * ROWB + row * ROWB + seg * 16,
                 Bhi + (size_t)(n0 + row) * EMB + k0 + seg * 8);
        }
        pd_cp_commit();
    };

    load_stage(0);

    for (int s = 0; s < NSTG; s++) {
        if (s + 1 < NSTG) { load_stage(s + 1); pd_cp_wait(1); }
        else              pd_cp_wait(0);
        __syncthreads();

        const int buf = s & 1;
        const char* sa_hi = sm + buf * BUFSZ;
        const char* sa_lo = sa_hi + BM * ROWB;
        const char* sb_hi = sm + buf * BUFSZ + NA * BM * ROWB;

#pragma unroll
        for (int kk = 0; kk < 2; kk++) {
            uint32_t Ah[2][4], Al[2][4], Bh[4][2];
#pragma unroll
            for (int i = 0; i < 2; i++) {
                uint32_t off = (uint32_t)((wm * 32 + i * 16 + r4) * ROWB + t * 4 + kk * 32);
                Ah[i][0] = *(const uint32_t*)(sa_hi + off);
                Ah[i][1] = *(const uint32_t*)(sa_hi + off + 8 * ROWB);
                Ah[i][2] = *(const uint32_t*)(sa_hi + off + 16);
                Ah[i][3] = *(const uint32_t*)(sa_hi + off + 8 * ROWB + 16);
                if (LO) {
                    Al[i][0] = *(const uint32_t*)(sa_lo + off);
                    Al[i][1] = *(const uint32_t*)(sa_lo + off + 8 * ROWB);
                    Al[i][2] = *(const uint32_t*)(sa_lo + off + 16);
                    Al[i][3] = *(const uint32_t*)(sa_lo + off + 8 * ROWB + 16);
                }
            }
#pragma unroll
            for (int j = 0; j < 4; j++) {
                uint32_t off = (uint32_t)((wn * 32 + j * 8 + r4) * ROWB + t * 4 + kk * 32);
                Bh[j][0] = *(const uint32_t*)(sb_hi + off);
                Bh[j][1] = *(const uint32_t*)(sb_hi + off + 16);
            }
#pragma unroll
            for (int i = 0; i < 2; i++)
#pragma unroll
                for (int j = 0; j < 4; j++) {
                    pd_mma_fp16(acc[i][j], Ah[i], Bh[j]);
                    if (LO) pd_mma_fp16(acc[i][j], Al[i], Bh[j]);
                }
        }
        __syncthreads();
    }

#pragma unroll
    for (int i = 0; i < 2; i++) {
        int row = m0 + wm * 32 + i * 16 + r4;
#pragma unroll
        for (int j = 0; j < 4; j++) {
            int col = n0 + wn * 32 + j * 8 + t * 2;
            *(float2*)(C + (size_t)row * ldc + col)       = make_float2(acc[i][j][0], acc[i][j][1]);
            *(float2*)(C + (size_t)(row + 8) * ldc + col) = make_float2(acc[i][j][2], acc[i][j][3]);
        }
    }
}

// ---------------- pos_term = rel_pos_emb @ W_pos  (64x16) ----------------
__global__ void pos_kernel(const float* __restrict__ rel, const float* __restrict__ Wp)
{
    int i = threadIdx.x;
    if (i < DELTA * BD) {
        int j = i >> 4, c = i & 15;
        float s = 0.f;
#pragma unroll
        for (int k = 0; k < BD; k++)
            s = fmaf(rel[j * BD + k], Wp[k * BD + c], s);
        g_pos[i] = s;
    }
}

// ---------------- fused window attention: fp16 phase2 + HMMA phase3 --------
#define VSTRIDE 72      // halfs per val row (144 B, 16B-multiple)
#define PBSTRIDE 88     // halfs per PB row (176 B, 16B-multiple)

__global__ __launch_bounds__(512) void fused_kernel(
    const float* __restrict__ W_strain, const float* __restrict__ W_dmg,
    const float* __restrict__ b_dmg,    const float* __restrict__ W_bond,
    const float* __restrict__ W_dmg_out, const float* __restrict__ b_dmg_out)
{
    __shared__ __align__(16) __half s_vh[80 * VSTRIDE];   // 11.25 KB
    __shared__ __align__(16) __half s_vl[80 * VSTRIDE];   // 11.25 KB
    __shared__ float   s_disp[NROWS * BD];                // 5.1 KB
    __shared__ float2  s_W2 [BD * 16];                    // 2 KB
    __shared__ __half2 s_PT [16 * NROWS];                 // 5.1 KB  [c][r] (bond,dmg)
    __shared__ __half2 s_ppT[16 * DELTA];                 // 4 KB    [c][j] (pos,b_dmg)
    __shared__ __align__(16) __half s_PBh[16 * PBSTRIDE]; // 2.8 KB
    __shared__ __align__(16) __half s_PBl[16 * PBSTRIDE]; // 2.8 KB
    __shared__ __half2 s_wout2[16];
    __shared__ float   s_inv[16];

    const int b  = blockIdx.z;
    const int h  = blockIdx.y;
    const int t0 = blockIdx.x * TTILE;
    const int tid = threadIdx.x;
    const int base_s = t0 - (DELTA - 1);

    // ---- phase 0: loads + zero-init ----
    for (int i = tid; i < NROWS * (HS / 4); i += 512) {
        int r  = i >> 4;
        int c4 = (i & 15) * 4;
        int s  = base_s + r;
        float4 v = make_float4(0.f, 0.f, 0.f, 0.f);
        if (s >= 0)
            v = *(const float4*)(g_val + (size_t)(b * SEQ + s) * EMB + h * HS + c4);
        uint32_t h01, l01, h23, l23;
        pd_split2h(v.x, v.y, h01, l01);
        pd_split2h(v.z, v.w, h23, l23);
        *(uint2*)(&s_vh[r * VSTRIDE + c4]) = make_uint2(h01, h23);
        *(uint2*)(&s_vl[r * VSTRIDE + c4]) = make_uint2(l01, l23);
    }
    if (tid < 32) {   // zero pad row 79 of val window
        *(uint32_t*)(&s_vh[79 * VSTRIDE + tid * 2]) = 0;
        *(uint32_t*)(&s_vl[79 * VSTRIDE + tid * 2]) = 0;
    }
    for (int i = tid; i < (16 * PBSTRIDE) / 2; i += 512) {
        *(uint32_t*)(&s_PBh[2 * i]) = 0;
        *(uint32_t*)(&s_PBl[2 * i]) = 0;
    }
    for (int i = tid; i < NROWS * (BD / 4); i += 512) {
        int r  = i >> 2;
        int c4 = (i & 3) * 4;
        int s  = base_s + r;
        float4 v = make_float4(0.f, 0.f, 0.f, 0.f);
        if (s >= 0)
            v = *(const float4*)(g_disp + (size_t)(b * SEQ + s) * (NH * BD) + h * BD + c4);
        *(float4*)(s_disp + r * BD + c4) = v;
    }
    if (tid < BD * 16)
        s_W2[tid] = make_float2(W_strain[tid], W_dmg[tid]);
    if (tid < 16)
        s_wout2[tid] = __floats2half2_rn(0.5f * W_bond[tid], 0.5f * W_dmg_out[tid]);
    for (int i = tid; i < 16 * DELTA; i += 512) {
        int c = i >> 6, j = i & 63;
        s_ppT[i] = __floats2half2_rn(g_pos[j * BD + c], b_dmg[c]);
    }
    __syncthreads();

    // ---- phase 1: PT[c][r] = (disp_r . Ws_c, disp_r . Wd_c) as half2 ----
    for (int i = tid; i < NROWS * 16; i += 512) {
        int r = i >> 4, c = i & 15;
        u64 acc = 0;
#pragma unroll
        for (int k = 0; k < BD; k++)
            acc = pd_fma2(pd_dupf(s_disp[r * BD + k]), *(const u64*)(&s_W2[k * 16 + c]), acc);
        float sx, sy; pd_unpack2(acc, sx, sy);
        s_PT[c * NROWS + r] = __floats2half2_rn(sx, sy);
    }
    __syncthreads();

    // ---- phase 2: logits (lane = j; two halves j, j+32), fp16 math ----
    const int wid  = tid >> 5;
    const int lane = tid & 31;
    const int t    = t0 + wid;

    const __half2 C0h = __float2half2_rn(0.7978845608f);
    const __half2 C1h = __float2half2_rn(0.0356774081f);
    const float c0  = 0.5f * b_dmg_out[0];
    const float L2E = 1.44269504089f, N5L2E = -7.21347520444f;

    __half2 accA = __float2half2_rn(0.f);
    __half2 accB = accA;

#pragma unroll
    for (int c = 0; c < 16; c++) {
        const __half2* Pc  = &s_PT[c * NROWS + wid];
        const __half2* ppc = &s_ppT[c * DELTA];
        const __half2 pre = Pc[DELTA - 1];
        const __half2 w2  = s_wout2[c];
        {
            __half2 xx = __hsub2(__hadd2(Pc[lane], ppc[lane]), pre);
            __half2 u  = __hmul2(xx, xx);
            __half2 t1 = __hfma2(u, C1h, C0h);
            __half2 th = pd_tanh2(__hmul2(xx, t1));
            __half2 m  = __hfma2(th, xx, xx);
            accA = __hfma2(m, w2, accA);
        }
        {
            __half2 xx = __hsub2(__hadd2(Pc[lane + 32], ppc[lane + 32]), pre);
            __half2 u  = __hmul2(xx, xx);
            __half2 t1 = __hfma2(u, C1h, C0h);
            __half2 th = pd_tanh2(__hmul2(xx, t1));
            __half2 m  = __hfma2(th, xx, xx);
            accB = __hfma2(m, w2, accB);
        }
    }

    const int jstart = (t < DELTA - 1) ? (DELTA - 1 - t) : 0;

    float p0, p1;
    {
        float bond = __low2float(accA), dm = __high2float(accA);
        float th2 = pd_tanhf(fmaf(dm, 0.5f, c0));
        float lt  = fmaf(th2, -5.f, bond);
        p0 = pd_ex2(fmaf(lt, L2E, N5L2E));
        if (lane < jstart) p0 = 0.f;
    }
    {
        float bond = __low2float(accB), dm = __high2float(accB);
        float th2 = pd_tanhf(fmaf(dm, 0.5f, c0));
        float lt  = fmaf(th2, -5.f, bond);
        p1 = pd_ex2(fmaf(lt, L2E, N5L2E));
        if (lane + 32 < jstart) p1 = 0.f;
    }

    // scatter p (hi + residual) into PB band
    {
        __half ph0 = __float2half_rn(p0);
        __half pl0 = __float2half_rn(p0 - __half2float(ph0));
        __half ph1 = __float2half_rn(p1);
        __half pl1 = __float2half_rn(p1 - __half2float(ph1));
        int bcol = wid * PBSTRIDE + wid + lane;
        s_PBh[bcol] = ph0;       s_PBl[bcol] = pl0;
        s_PBh[bcol + 32] = ph1;  s_PBl[bcol + 32] = pl1;
    }

    float ssum = p0 + p1;
#pragma unroll
    for (int off = 1; off < 32; off <<= 1)
        ssum += __shfl_xor_sync(0xffffffffu, ssum, off);
    if (lane == 0)
        s_inv[wid] = __fdividef(1.0f, ssum);
    __syncthreads();

    // ---- phase 3: out[16][64] = PB[16][80] x val[80][64] via HMMA ----
    if (wid < 8) {
        const int nb = wid;
        float acc[4] = {0.f, 0.f, 0.f, 0.f};
        const uint32_t pbh = pd_smem_u32(s_PBh), pbl = pd_smem_u32(s_PBl);
        const uint32_t vhb = pd_smem_u32(s_vh),  vlb = pd_smem_u32(s_vl);
        const uint32_t rA = (uint32_t)(lane & 15);
        const uint32_t cA = (uint32_t)((lane >> 4) * 8);
#pragma unroll
        for (int kk = 0; kk < 5; kk++) {
            uint32_t offA = (rA * PBSTRIDE + kk * 16 + cA) * 2;
            uint32_t offB = ((kk * 16 + (lane & 15)) * VSTRIDE + nb * 8) * 2;
            uint32_t Ah[4], Al[4], Bh[2], Bl[2];
            PD_LDSM_X4(Ah, pbh + offA);
            PD_LDSM_X4(Al, pbl + offA);
            PD_LDSM_X2T(Bh, vhb + offB);
            PD_LDSM_X2T(Bl, vlb + offB);
            pd_mma_fp16(acc, Ah, Bh);
            pd_mma_fp16(acc, Ah, Bl);
            pd_mma_fp16(acc, Al, Bh);
        }
        const int r0 = lane >> 2;
        const int e  = nb * 8 + (lane & 3) * 2;
        const float inv0 = s_inv[r0], inv1 = s_inv[r0 + 8];
        uint32_t hi, lo;
        size_t ob0 = (size_t)(b * SEQ + t0 + r0) * EMB + h * HS + e;
        pd_split2h(acc[0] * inv0, acc[1] * inv0, hi, lo);
        *(uint32_t*)(&g_athi[ob0]) = hi;
        *(uint32_t*)(&g_atlo[ob0]) = lo;
        size_t ob1 = ob0 + (size_t)8 * EMB;
        pd_split2h(acc[2] * inv1, acc[3] * inv1, hi, lo);
        *(uint32_t*)(&g_athi[ob1]) = hi;
        *(uint32_t*)(&g_atlo[ob1]) = lo;
    }
}

// ---------------- launch ----------------
extern "C" void kernel_launch(void* const* d_in, const int* in_sizes, int n_in,
                              void* d_out, int out_size)
{
    const float* x         = (const float*)d_in[0];
    const float* W_disp    = (const float*)d_in[1];
    const float* W_val     = (const float*)d_in[2];
    const float* rel       = (const float*)d_in[3];
    const float* W_strain  = (const float*)d_in[4];
    const float* W_pos     = (const float*)d_in[5];
    const float* W_bond    = (const float*)d_in[6];
    const float* W_dmg     = (const float*)d_in[7];
    const float* b_dmg     = (const float*)d_in[8];
    const float* W_dmg_out = (const float*)d_in[9];
    const float* b_dmg_out = (const float*)d_in[10];
    const float* W_cproj   = (const float*)d_in[11];
    float* out = (float*)d_out;

    float *disp_p, *val_p;
    __half *xhi, *xlo, *athi, *atlo, *bthi, *cthi;
    cudaGetSymbolAddress((void**)&disp_p, g_disp);
    cudaGetSymbolAddress((void**)&val_p,  g_val);
    cudaGetSymbolAddress((void**)&xhi, g_xhi);   cudaGetSymbolAddress((void**)&xlo, g_xlo);
    cudaGetSymbolAddress((void**)&athi, g_athi); cudaGetSymbolAddress((void**)&atlo, g_atlo);
    cudaGetSymbolAddress((void**)&bthi, g_bthi); cudaGetSymbolAddress((void**)&cthi, g_cthi);

    const int SMEM_BIG   = (2 * 128 + 128) * ROWB * 2;   // 61440
    const int SMEM_SMALL = (64 + 64) * ROWB * 2;         // 20480
    cudaFuncSetAttribute((const void*)gemm_kernel<128, 128, 512, 4, true>,
                         cudaFuncAttributeMaxDynamicSharedMemorySize, SMEM_BIG);
    cudaFuncSetAttribute((const void*)gemm_kernel<64, 64, 128, 2, false>,
                         cudaFuncAttributeMaxDynamicSharedMemorySize, SMEM_SMALL);

    pos_kernel<<<1, 1024>>>(rel, W_pos);
    split_x_kernel<<<(MTOT * EMB / 2) / 512, 512>>>(x);
    splitT_kernel<<<dim3((NH * BD + EMB) / 32, EMB / 32), dim3(32, 8)>>>(
        W_disp, NH * BD, W_val, EMB, bthi);
    splitT_kernel<<<dim3(EMB / 32, EMB / 32), dim3(32, 8)>>>(
        W_cproj, EMB, W_cproj, EMB, cthi);

    gemm_kernel<64, 64, 128, 2, false><<<dim3((NH * BD) / 64, MTOT / 64), 128, SMEM_SMALL>>>(
        xhi, xlo, bthi, disp_p, NH * BD);
    gemm_kernel<128, 128, 512, 4, true><<<dim3(EMB / 128, MTOT / 128), 512, SMEM_BIG>>>(
        xhi, xlo, bthi + (size_t)(NH * BD) * EMB, val_p, EMB);
    fused_kernel<<<dim3(SEQ / TTILE, NH, BATCH), 512>>>(W_strain, W_dmg, b_dmg,
                                                        W_bond, W_dmg_out, b_dmg_out);
    gemm_kernel<128, 128, 512, 4, true><<<dim3(EMB / 128, MTOT / 128), 512, SMEM_BIG>>>(
        athi, atlo, cthi, out, EMB);
}

// round 11
// speedup vs baseline: 4.4803x; 1.1916x over previous
#include <cuda_runtime.h>
#include <cuda_fp16.h>
#include <cstdint>
#include <math.h>

#define BATCH 2
#define SEQ   1024
#define EMB   1024
#define NH    16
#define HS    64
#define BD    16
#define DELTA 64
#define TTILE 16
#define NROWS (TTILE + DELTA - 1)   // 79
#define MTOT  (BATCH * SEQ)         // 2048
#define NDV   1280                  // disp (256) ++ val (1024) columns

// ---------------- scratch (static device memory; no allocs) ----------------
__device__ float g_dv [MTOT * NDV];                // [disp | val] fp32
__device__ float g_pos[DELTA * BD];
__device__ __half g_xhi [MTOT * EMB];
__device__ __half g_athi[MTOT * EMB];
__device__ __half g_bthi[NDV * EMB];               // [W_disp^T ++ W_val^T]
__device__ __half g_cthi[EMB * EMB];               // W_cproj^T

// ---------------- helpers (pd_ prefix: no vendor-header collisions) --------
typedef unsigned long long u64;

__device__ __forceinline__ u64 pd_dupf(float v) {
    u64 r; asm("mov.b64 %0, {%1, %1};" : "=l"(r) : "f"(v)); return r;
}
__device__ __forceinline__ void pd_unpack2(u64 v, float& a, float& b) {
    asm("mov.b64 {%0, %1}, %2;" : "=f"(a), "=f"(b) : "l"(v));
}
__device__ __forceinline__ u64 pd_fma2(u64 a, u64 b, u64 c) {
    u64 r; asm("fma.rn.f32x2 %0, %1, %2, %3;" : "=l"(r) : "l"(a), "l"(b), "l"(c)); return r;
}
__device__ __forceinline__ float pd_tanhf(float x) {
    float r; asm("tanh.approx.f32 %0, %1;" : "=f"(r) : "f"(x)); return r;
}
__device__ __forceinline__ __half2 pd_tanh2(__half2 x) {
    uint32_t xi = *reinterpret_cast<uint32_t*>(&x), ri;
    asm("tanh.approx.f16x2 %0, %1;" : "=r"(ri) : "r"(xi));
    return *reinterpret_cast<__half2*>(&ri);
}
__device__ __forceinline__ float pd_ex2(float x) {
    float r; asm("ex2.approx.f32 %0, %1;" : "=f"(r) : "f"(x)); return r;
}
__device__ __forceinline__ uint32_t pd_smem_u32(const void* p) {
    uint32_t a;
    asm("{ .reg .u64 t; cvta.to.shared.u64 t, %1; cvt.u32.u64 %0, t; }" : "=r"(a) : "l"(p));
    return a;
}
__device__ __forceinline__ void pd_cp16(uint32_t dst, const void* src) {
    asm volatile("{ .reg .u64 g; cvta.to.global.u64 g, %1; cp.async.cg.shared.global [%0], [g], 16; }"
                 :: "r"(dst), "l"(src) : "memory");
}
__device__ __forceinline__ void pd_cp_commit() { asm volatile("cp.async.commit_group;" ::: "memory"); }
__device__ __forceinline__ void pd_cp_wait(int pending) {
    if (pending) asm volatile("cp.async.wait_group 1;" ::: "memory");
    else         asm volatile("cp.async.wait_group 0;" ::: "memory");
}

__device__ __forceinline__ void pd_split2h(float a, float b, uint32_t& hi, uint32_t& lo) {
    __half2 h2 = __floats2half2_rn(a, b);
    float ra = a - __half2float(h2.x);
    float rb = b - __half2float(h2.y);
    __half2 l2 = __floats2half2_rn(ra, rb);
    hi = *reinterpret_cast<uint32_t*>(&h2);
    lo = *reinterpret_cast<uint32_t*>(&l2);
}

__device__ __forceinline__ void pd_mma_fp16(float* c, const uint32_t* a, const uint32_t* b) {
    asm volatile(
        "mma.sync.aligned.m16n8k16.row.col.f32.f16.f16.f32 "
        "{%0,%1,%2,%3}, {%4,%5,%6,%7}, {%8,%9}, {%0,%1,%2,%3};"
        : "+f"(c[0]), "+f"(c[1]), "+f"(c[2]), "+f"(c[3])
        : "r"(a[0]), "r"(a[1]), "r"(a[2]), "r"(a[3]), "r"(b[0]), "r"(b[1]));
}

#define PD_LDSM_X4(r, a) \
    asm volatile("ldmatrix.sync.aligned.m8n8.x4.shared.b16 {%0,%1,%2,%3}, [%4];" \
                 : "=r"((r)[0]), "=r"((r)[1]), "=r"((r)[2]), "=r"((r)[3]) : "r"(a))
#define PD_LDSM_X2T(r, a) \
    asm volatile("ldmatrix.sync.aligned.m8n8.x2.trans.shared.b16 {%0,%1}, [%2];" \
                 : "=r"((r)[0]), "=r"((r)[1]) : "r"(a))

// ---------------- conversion kernels ----------------
// x -> fp16 hi only (1 float4 per thread)
__global__ __launch_bounds__(512) void split_x_kernel(const float* __restrict__ x) {
    size_t i = (size_t)blockIdx.x * 512 + threadIdx.x;   // over 512K float4
    float4 v = ((const float4*)x)[i];
    __half2 a = __floats2half2_rn(v.x, v.y);
    __half2 b = __floats2half2_rn(v.z, v.w);
    ((__half2*)g_xhi)[2 * i]     = a;
    ((__half2*)g_xhi)[2 * i + 1] = b;
}

// merged transpose+convert: n in [0,256) W_disp, [256,1280) W_val -> bthi;
// n in [1280,2304) W_cproj -> cthi.
__global__ void splitT_kernel(const float* __restrict__ Wd,
                              const float* __restrict__ Wv,
                              const float* __restrict__ Wc)
{
    __shared__ float tile[32][33];
    const int k0 = blockIdx.y * 32;
    const int n0 = blockIdx.x * 32;
    const int tx = threadIdx.x, ty = threadIdx.y;   // 32 x 8
#pragma unroll
    for (int q = 0; q < 4; q++) {
        int k = k0 + ty + 8 * q;
        int n = n0 + tx;
        float v;
        if (n < 256)        v = Wd[(size_t)k * 256 + n];
        else if (n < 1280)  v = Wv[(size_t)k * EMB + (n - 256)];
        else                v = Wc[(size_t)k * EMB + (n - 1280)];
        tile[ty + 8 * q][tx] = v;
    }
    __syncthreads();
#pragma unroll
    for (int q = 0; q < 4; q++) {
        int n = n0 + ty + 8 * q;
        int k = k0 + tx;
        __half hv = __float2half_rn(tile[tx][ty + 8 * q]);
        if (n < 1280) g_bthi[(size_t)n * EMB + k] = hv;
        else          g_cthi[(size_t)(n - 1280) * EMB + k] = hv;
    }
}

// ---------------- fp16 HMMA GEMM (hi-only operands) ----------------
#define ROWB 80
#define NSTG 32

template<int BM, int BN, int THREADS, int WN>
__global__ __launch_bounds__(THREADS) void gemm_kernel(
    const __half* __restrict__ Ahi, const __half* __restrict__ Bhi,
    float* __restrict__ C, int ldc)
{
    extern __shared__ __align__(16) char sm[];
    const uint32_t sbase = pd_smem_u32(sm);
    const int tid  = threadIdx.x;
    const int wid  = tid >> 5;
    const int lane = tid & 31;
    const int wm   = wid / WN;
    const int wn   = wid % WN;
    const int m0 = blockIdx.y * BM;
    const int n0 = blockIdx.x * BN;
    const int r4 = lane >> 2;
    const int t  = lane & 3;

    const int BUFSZ = (BM + BN) * ROWB;

    float acc[2][4][4];
#pragma unroll
    for (int i = 0; i < 2; i++)
#pragma unroll
        for (int j = 0; j < 4; j++)
#pragma unroll
            for (int q = 0; q < 4; q++) acc[i][j][q] = 0.f;

    auto load_stage = [&](int s) {
        const int buf = s & 1;
        const int k0 = s * 32;
        uint32_t base = sbase + buf * BUFSZ;
#pragma unroll
        for (int i = tid; i < BM * 4; i += THREADS) {
            int row = i >> 2, seg = i & 3;
            pd_cp16(base + row * ROWB + seg * 16,
                    Ahi + (size_t)(m0 + row) * EMB + k0 + seg * 8);
        }
#pragma unroll
        for (int i = tid; i < BN * 4; i += THREADS) {
            int row = i >> 2, seg = i & 3;
            pd_cp16(base + BM * ROWB + row * ROWB + seg * 16,
                    Bhi + (size_t)(n0 + row) * EMB + k0 + seg * 8);
        }
        pd_cp_commit();
    };

    load_stage(0);

    for (int s = 0; s < NSTG; s++) {
        if (s + 1 < NSTG) { load_stage(s + 1); pd_cp_wait(1); }
        else              pd_cp_wait(0);
        __syncthreads();

        const int buf = s & 1;
        const char* sa = sm + buf * BUFSZ;
        const char* sb = sm + buf * BUFSZ + BM * ROWB;

#pragma unroll
        for (int kk = 0; kk < 2; kk++) {
            uint32_t Ah[2][4], Bh[4][2];
#pragma unroll
            for (int i = 0; i < 2; i++) {
                uint32_t off = (uint32_t)((wm * 32 + i * 16 + r4) * ROWB + t * 4 + kk * 32);
                Ah[i][0] = *(const uint32_t*)(sa + off);
                Ah[i][1] = *(const uint32_t*)(sa + off + 8 * ROWB);
                Ah[i][2] = *(const uint32_t*)(sa + off + 16);
                Ah[i][3] = *(const uint32_t*)(sa + off + 8 * ROWB + 16);
            }
#pragma unroll
            for (int j = 0; j < 4; j++) {
                uint32_t off = (uint32_t)((wn * 32 + j * 8 + r4) * ROWB + t * 4 + kk * 32);
                Bh[j][0] = *(const uint32_t*)(sb + off);
                Bh[j][1] = *(const uint32_t*)(sb + off + 16);
            }
#pragma unroll
            for (int i = 0; i < 2; i++)
#pragma unroll
                for (int j = 0; j < 4; j++)
                    pd_mma_fp16(acc[i][j], Ah[i], Bh[j]);
        }
        __syncthreads();
    }

#pragma unroll
    for (int i = 0; i < 2; i++) {
        int row = m0 + wm * 32 + i * 16 + r4;
#pragma unroll
        for (int j = 0; j < 4; j++) {
            int col = n0 + wn * 32 + j * 8 + t * 2;
            *(float2*)(C + (size_t)row * ldc + col)       = make_float2(acc[i][j][0], acc[i][j][1]);
            *(float2*)(C + (size_t)(row + 8) * ldc + col) = make_float2(acc[i][j][2], acc[i][j][3]);
        }
    }
}

// ---------------- pos_term = rel_pos_emb @ W_pos  (64x16) ----------------
__global__ void pos_kernel(const float* __restrict__ rel, const float* __restrict__ Wp)
{
    int i = threadIdx.x;
    if (i < DELTA * BD) {
        int j = i >> 4, c = i & 15;
        float s = 0.f;
#pragma unroll
        for (int k = 0; k < BD; k++)
            s = fmaf(rel[j * BD + k], Wp[k * BD + c], s);
        g_pos[i] = s;
    }
}

// ---------------- fused window attention: fp16 phase2 + HMMA phase3 --------
#define VSTRIDE 72      // halfs per val row (144 B, 16B-multiple)
#define PBSTRIDE 88     // halfs per PB row (176 B, 16B-multiple)

__global__ __launch_bounds__(512) void fused_kernel(
    const float* __restrict__ W_strain, const float* __restrict__ W_dmg,
    const float* __restrict__ b_dmg,    const float* __restrict__ W_bond,
    const float* __restrict__ W_dmg_out, const float* __restrict__ b_dmg_out)
{
    __shared__ __align__(16) __half s_vh[80 * VSTRIDE];   // 11.25 KB
    __shared__ __align__(16) __half s_vl[80 * VSTRIDE];   // 11.25 KB
    __shared__ float   s_disp[NROWS * BD];                // 5.1 KB
    __shared__ float2  s_W2 [BD * 16];                    // 2 KB
    __shared__ __half2 s_PT [16 * NROWS];                 // 5.1 KB  [c][r] (bond,dmg)
    __shared__ __half2 s_ppT[16 * DELTA];                 // 4 KB    [c][j] (pos,b_dmg)
    __shared__ __align__(16) __half s_PBh[16 * PBSTRIDE]; // 2.8 KB
    __shared__ __align__(16) __half s_PBl[16 * PBSTRIDE]; // 2.8 KB
    __shared__ __half2 s_wout2[16];
    __shared__ float   s_inv[16];

    const int b  = blockIdx.z;
    const int h  = blockIdx.y;
    const int t0 = blockIdx.x * TTILE;
    const int tid = threadIdx.x;
    const int base_s = t0 - (DELTA - 1);

    // ---- phase 0: loads + zero-init ----
    for (int i = tid; i < NROWS * (HS / 4); i += 512) {
        int r  = i >> 4;
        int c4 = (i & 15) * 4;
        int s  = base_s + r;
        float4 v = make_float4(0.f, 0.f, 0.f, 0.f);
        if (s >= 0)
            v = *(const float4*)(g_dv + (size_t)(b * SEQ + s) * NDV + 256 + h * HS + c4);
        uint32_t h01, l01, h23, l23;
        pd_split2h(v.x, v.y, h01, l01);
        pd_split2h(v.z, v.w, h23, l23);
        *(uint2*)(&s_vh[r * VSTRIDE + c4]) = make_uint2(h01, h23);
        *(uint2*)(&s_vl[r * VSTRIDE + c4]) = make_uint2(l01, l23);
    }
    if (tid < 32) {   // zero pad row 79 of val window
        *(uint32_t*)(&s_vh[79 * VSTRIDE + tid * 2]) = 0;
        *(uint32_t*)(&s_vl[79 * VSTRIDE + tid * 2]) = 0;
    }
    for (int i = tid; i < (16 * PBSTRIDE) / 2; i += 512) {
        *(uint32_t*)(&s_PBh[2 * i]) = 0;
        *(uint32_t*)(&s_PBl[2 * i]) = 0;
    }
    for (int i = tid; i < NROWS * (BD / 4); i += 512) {
        int r  = i >> 2;
        int c4 = (i & 3) * 4;
        int s  = base_s + r;
        float4 v = make_float4(0.f, 0.f, 0.f, 0.f);
        if (s >= 0)
            v = *(const float4*)(g_dv + (size_t)(b * SEQ + s) * NDV + h * BD + c4);
        *(float4*)(s_disp + r * BD + c4) = v;
    }
    if (tid < BD * 16)
        s_W2[tid] = make_float2(W_strain[tid], W_dmg[tid]);
    if (tid < 16)
        s_wout2[tid] = __floats2half2_rn(0.5f * W_bond[tid], 0.5f * W_dmg_out[tid]);
    for (int i = tid; i < 16 * DELTA; i += 512) {
        int c = i >> 6, j = i & 63;
        s_ppT[i] = __floats2half2_rn(g_pos[j * BD + c], b_dmg[c]);
    }
    __syncthreads();

    // ---- phase 1: PT[c][r] = (disp_r . Ws_c, disp_r . Wd_c) as half2 ----
    for (int i = tid; i < NROWS * 16; i += 512) {
        int r = i >> 4, c = i & 15;
        u64 acc = 0;
#pragma unroll
        for (int k = 0; k < BD; k++)
            acc = pd_fma2(pd_dupf(s_disp[r * BD + k]), *(const u64*)(&s_W2[k * 16 + c]), acc);
        float sx, sy; pd_unpack2(acc, sx, sy);
        s_PT[c * NROWS + r] = __floats2half2_rn(sx, sy);
    }
    __syncthreads();

    // ---- phase 2: logits (lane = j; two halves j, j+32), fp16 math ----
    const int wid  = tid >> 5;
    const int lane = tid & 31;
    const int t    = t0 + wid;

    const __half2 C0h = __float2half2_rn(0.7978845608f);
    const __half2 C1h = __float2half2_rn(0.0356774081f);
    const float c0  = 0.5f * b_dmg_out[0];
    const float L2E = 1.44269504089f, N5L2E = -7.21347520444f;

    __half2 accA = __float2half2_rn(0.f);
    __half2 accB = accA;

#pragma unroll
    for (int c = 0; c < 16; c++) {
        const __half2* Pc  = &s_PT[c * NROWS + wid];
        const __half2* ppc = &s_ppT[c * DELTA];
        const __half2 pre = Pc[DELTA - 1];
        const __half2 w2  = s_wout2[c];
        {
            __half2 xx = __hsub2(__hadd2(Pc[lane], ppc[lane]), pre);
            __half2 u  = __hmul2(xx, xx);
            __half2 t1 = __hfma2(u, C1h, C0h);
            __half2 th = pd_tanh2(__hmul2(xx, t1));
            __half2 m  = __hfma2(th, xx, xx);
            accA = __hfma2(m, w2, accA);
        }
        {
            __half2 xx = __hsub2(__hadd2(Pc[lane + 32], ppc[lane + 32]), pre);
            __half2 u  = __hmul2(xx, xx);
            __half2 t1 = __hfma2(u, C1h, C0h);
            __half2 th = pd_tanh2(__hmul2(xx, t1));
            __half2 m  = __hfma2(th, xx, xx);
            accB = __hfma2(m, w2, accB);
        }
    }

    const int jstart = (t < DELTA - 1) ? (DELTA - 1 - t) : 0;

    float p0, p1;
    {
        float bond = __low2float(accA), dm = __high2float(accA);
        float th2 = pd_tanhf(fmaf(dm, 0.5f, c0));
        float lt  = fmaf(th2, -5.f, bond);
        p0 = pd_ex2(fmaf(lt, L2E, N5L2E));
        if (lane < jstart) p0 = 0.f;
    }
    {
        float bond = __low2float(accB), dm = __high2float(accB);
        float th2 = pd_tanhf(fmaf(dm, 0.5f, c0));
        float lt  = fmaf(th2, -5.f, bond);
        p1 = pd_ex2(fmaf(lt, L2E, N5L2E));
        if (lane + 32 < jstart) p1 = 0.f;
    }

    // scatter p (hi + residual) into PB band
    {
        __half ph0 = __float2half_rn(p0);
        __half pl0 = __float2half_rn(p0 - __half2float(ph0));
        __half ph1 = __float2half_rn(p1);
        __half pl1 = __float2half_rn(p1 - __half2float(ph1));
        int bcol = wid * PBSTRIDE + wid + lane;
        s_PBh[bcol] = ph0;       s_PBl[bcol] = pl0;
        s_PBh[bcol + 32] = ph1;  s_PBl[bcol + 32] = pl1;
    }

    float ssum = p0 + p1;
#pragma unroll
    for (int off = 1; off < 32; off <<= 1)
        ssum += __shfl_xor_sync(0xffffffffu, ssum, off);
    if (lane == 0)
        s_inv[wid] = __fdividef(1.0f, ssum);
    __syncthreads();

    // ---- phase 3: out[16][64] = PB[16][80] x val[80][64] via HMMA ----
    if (wid < 8) {
        const int nb = wid;
        float acc[4] = {0.f, 0.f, 0.f, 0.f};
        const uint32_t pbh = pd_smem_u32(s_PBh), pbl = pd_smem_u32(s_PBl);
        const uint32_t vhb = pd_smem_u32(s_vh),  vlb = pd_smem_u32(s_vl);
        const uint32_t rA = (uint32_t)(lane & 15);
        const uint32_t cA = (uint32_t)((lane >> 4) * 8);
#pragma unroll
        for (int kk = 0; kk < 5; kk++) {
            uint32_t offA = (rA * PBSTRIDE + kk * 16 + cA) * 2;
            uint32_t offB = ((kk * 16 + (lane & 15)) * VSTRIDE + nb * 8) * 2;
            uint32_t Ah[4], Al[4], Bh[2], Bl[2];
            PD_LDSM_X4(Ah, pbh + offA);
            PD_LDSM_X4(Al, pbl + offA);
            PD_LDSM_X2T(Bh, vhb + offB);
            PD_LDSM_X2T(Bl, vlb + offB);
            pd_mma_fp16(acc, Ah, Bh);
            pd_mma_fp16(acc, Ah, Bl);
            pd_mma_fp16(acc, Al, Bh);
        }
        const int r0 = lane >> 2;
        const int e  = nb * 8 + (lane & 3) * 2;
        const float inv0 = s_inv[r0], inv1 = s_inv[r0 + 8];
        size_t ob0 = (size_t)(b * SEQ + t0 + r0) * EMB + h * HS + e;
        *(__half2*)(&g_athi[ob0]) = __floats2half2_rn(acc[0] * inv0, acc[1] * inv0);
        size_t ob1 = ob0 + (size_t)8 * EMB;
        *(__half2*)(&g_athi[ob1]) = __floats2half2_rn(acc[2] * inv1, acc[3] * inv1);
    }
}

// ---------------- launch ----------------
extern "C" void kernel_launch(void* const* d_in, const int* in_sizes, int n_in,
                              void* d_out, int out_size)
{
    const float* x         = (const float*)d_in[0];
    const float* W_disp    = (const float*)d_in[1];
    const float* W_val     = (const float*)d_in[2];
    const float* rel       = (const float*)d_in[3];
    const float* W_strain  = (const float*)d_in[4];
    const float* W_pos     = (const float*)d_in[5];
    const float* W_bond    = (const float*)d_in[6];
    const float* W_dmg     = (const float*)d_in[7];
    const float* b_dmg     = (const float*)d_in[8];
    const float* W_dmg_out = (const float*)d_in[9];
    const float* b_dmg_out = (const float*)d_in[10];
    const float* W_cproj   = (const float*)d_in[11];
    float* out = (float*)d_out;

    float* dv_p;
    __half *xhi, *athi, *bthi, *cthi;
    cudaGetSymbolAddress((void**)&dv_p, g_dv);
    cudaGetSymbolAddress((void**)&xhi, g_xhi);
    cudaGetSymbolAddress((void**)&athi, g_athi);
    cudaGetSymbolAddress((void**)&bthi, g_bthi);
    cudaGetSymbolAddress((void**)&cthi, g_cthi);

    const int SMEM_GEMM = (128 + 128) * ROWB * 2;   // 40960
    cudaFuncSetAttribute((const void*)gemm_kernel<128, 128, 512, 4>,
                         cudaFuncAttributeMaxDynamicSharedMemorySize, SMEM_GEMM);

    pos_kernel<<<1, 1024>>>(rel, W_pos);
    split_x_kernel<<<(MTOT * EMB / 4) / 512, 512>>>(x);
    splitT_kernel<<<dim3(2304 / 32, EMB / 32), dim3(32, 8)>>>(W_disp, W_val, W_cproj);

    // combined disp+val GEMM: C[2048][1280] = x * [W_disp | W_val]
    gemm_kernel<128, 128, 512, 4><<<dim3(NDV / 128, MTOT / 128), 512, SMEM_GEMM>>>(
        xhi, bthi, dv_p, NDV);
    fused_kernel<<<dim3(SEQ / TTILE, NH, BATCH), 512>>>(W_strain, W_dmg, b_dmg,
                                                        W_bond, W_dmg_out, b_dmg_out);
    gemm_kernel<128, 128, 512, 4><<<dim3(EMB / 128, MTOT / 128), 512, SMEM_GEMM>>>(
        athi, cthi, out, EMB);
}

// round 12
// speedup vs baseline: 4.9578x; 1.1066x over previous
#include <cuda_runtime.h>
#include <cuda_fp16.h>
#include <cstdint>
#include <math.h>

#define BATCH 2
#define SEQ   1024
#define EMB   1024
#define NH    16
#define HS    64
#define BD    16
#define DELTA 64
#define TTILE 16
#define NROWS (TTILE + DELTA - 1)   // 79
#define MTOT  (BATCH * SEQ)         // 2048
#define NDV   1280                  // disp (256) ++ val (1024) columns

// ---------------- scratch (static device memory; no allocs) ----------------
__device__ float g_dv [MTOT * NDV];                // [disp | val] fp32
__device__ float g_pos[DELTA * BD];
__device__ __half g_xhi [MTOT * EMB];
__device__ __half g_athi[MTOT * EMB];
__device__ __half g_bthi[NDV * EMB];               // [W_disp^T ++ W_val^T]
__device__ __half g_cthi[EMB * EMB];               // W_cproj^T

// ---------------- helpers (pd_ prefix: no vendor-header collisions) --------
typedef unsigned long long u64;

__device__ __forceinline__ u64 pd_dupf(float v) {
    u64 r; asm("mov.b64 %0, {%1, %1};" : "=l"(r) : "f"(v)); return r;
}
__device__ __forceinline__ void pd_unpack2(u64 v, float& a, float& b) {
    asm("mov.b64 {%0, %1}, %2;" : "=f"(a), "=f"(b) : "l"(v));
}
__device__ __forceinline__ u64 pd_fma2(u64 a, u64 b, u64 c) {
    u64 r; asm("fma.rn.f32x2 %0, %1, %2, %3;" : "=l"(r) : "l"(a), "l"(b), "l"(c)); return r;
}
__device__ __forceinline__ float pd_tanhf(float x) {
    float r; asm("tanh.approx.f32 %0, %1;" : "=f"(r) : "f"(x)); return r;
}
__device__ __forceinline__ __half2 pd_tanh2(__half2 x) {
    uint32_t xi = *reinterpret_cast<uint32_t*>(&x), ri;
    asm("tanh.approx.f16x2 %0, %1;" : "=r"(ri) : "r"(xi));
    return *reinterpret_cast<__half2*>(&ri);
}
__device__ __forceinline__ float pd_ex2(float x) {
    float r; asm("ex2.approx.f32 %0, %1;" : "=f"(r) : "f"(x)); return r;
}
__device__ __forceinline__ uint32_t pd_smem_u32(const void* p) {
    uint32_t a;
    asm("{ .reg .u64 t; cvta.to.shared.u64 t, %1; cvt.u32.u64 %0, t; }" : "=r"(a) : "l"(p));
    return a;
}
__device__ __forceinline__ void pd_cp16(uint32_t dst, const void* src) {
    asm volatile("{ .reg .u64 g; cvta.to.global.u64 g, %1; cp.async.cg.shared.global [%0], [g], 16; }"
                 :: "r"(dst), "l"(src) : "memory");
}
__device__ __forceinline__ void pd_cp_commit() { asm volatile("cp.async.commit_group;" ::: "memory"); }
__device__ __forceinline__ void pd_cp_wait(int pending) {
    if (pending) asm volatile("cp.async.wait_group 1;" ::: "memory");
    else         asm volatile("cp.async.wait_group 0;" ::: "memory");
}

__device__ __forceinline__ void pd_split2h(float a, float b, uint32_t& hi, uint32_t& lo) {
    __half2 h2 = __floats2half2_rn(a, b);
    float ra = a - __half2float(h2.x);
    float rb = b - __half2float(h2.y);
    __half2 l2 = __floats2half2_rn(ra, rb);
    hi = *reinterpret_cast<uint32_t*>(&h2);
    lo = *reinterpret_cast<uint32_t*>(&l2);
}

__device__ __forceinline__ void pd_mma_fp16(float* c, const uint32_t* a, const uint32_t* b) {
    asm volatile(
        "mma.sync.aligned.m16n8k16.row.col.f32.f16.f16.f32 "
        "{%0,%1,%2,%3}, {%4,%5,%6,%7}, {%8,%9}, {%0,%1,%2,%3};"
        : "+f"(c[0]), "+f"(c[1]), "+f"(c[2]), "+f"(c[3])
        : "r"(a[0]), "r"(a[1]), "r"(a[2]), "r"(a[3]), "r"(b[0]), "r"(b[1]));
}

#define PD_LDSM_X4(r, a) \
    asm volatile("ldmatrix.sync.aligned.m8n8.x4.shared.b16 {%0,%1,%2,%3}, [%4];" \
                 : "=r"((r)[0]), "=r"((r)[1]), "=r"((r)[2]), "=r"((r)[3]) : "r"(a))
#define PD_LDSM_X2T(r, a) \
    asm volatile("ldmatrix.sync.aligned.m8n8.x2.trans.shared.b16 {%0,%1}, [%2];" \
                 : "=r"((r)[0]), "=r"((r)[1]) : "r"(a))

// ---------------- conversion kernels ----------------
__global__ __launch_bounds__(512) void split_x_kernel(const float* __restrict__ x) {
    size_t i = (size_t)blockIdx.x * 512 + threadIdx.x;   // over 512K float4
    float4 v = ((const float4*)x)[i];
    __half2 a = __floats2half2_rn(v.x, v.y);
    __half2 b = __floats2half2_rn(v.z, v.w);
    ((__half2*)g_xhi)[2 * i]     = a;
    ((__half2*)g_xhi)[2 * i + 1] = b;
}

// merged transpose+convert: n in [0,256) W_disp, [256,1280) W_val -> bthi;
// n in [1280,2304) W_cproj -> cthi.
__global__ void splitT_kernel(const float* __restrict__ Wd,
                              const float* __restrict__ Wv,
                              const float* __restrict__ Wc)
{
    __shared__ float tile[32][33];
    const int k0 = blockIdx.y * 32;
    const int n0 = blockIdx.x * 32;
    const int tx = threadIdx.x, ty = threadIdx.y;   // 32 x 8
#pragma unroll
    for (int q = 0; q < 4; q++) {
        int k = k0 + ty + 8 * q;
        int n = n0 + tx;
        float v;
        if (n < 256)        v = Wd[(size_t)k * 256 + n];
        else if (n < 1280)  v = Wv[(size_t)k * EMB + (n - 256)];
        else                v = Wc[(size_t)k * EMB + (n - 1280)];
        tile[ty + 8 * q][tx] = v;
    }
    __syncthreads();
#pragma unroll
    for (int q = 0; q < 4; q++) {
        int n = n0 + ty + 8 * q;
        int k = k0 + tx;
        __half hv = __float2half_rn(tile[tx][ty + 8 * q]);
        if (n < 1280) g_bthi[(size_t)n * EMB + k] = hv;
        else          g_cthi[(size_t)(n - 1280) * EMB + k] = hv;
    }
}

// ---------------- fp16 HMMA GEMM (hi-only operands) ----------------
// Warp layout: 4 (M) x WN warps; each warp covers 32 rows x (BN/4) cols.
// NFRAG = BN/4/8 n-fragments of 8 columns.
#define ROWB 80
#define NSTG 32

template<int BM, int BN, int THREADS, int WN>
__global__ __launch_bounds__(THREADS) void gemm_kernel(
    const __half* __restrict__ Ahi, const __half* __restrict__ Bhi,
    float* __restrict__ C, int ldc)
{
    extern __shared__ __align__(16) char sm[];
    const uint32_t sbase = pd_smem_u32(sm);
    const int tid  = threadIdx.x;
    const int wid  = tid >> 5;
    const int lane = tid & 31;
    const int wm   = wid / WN;
    const int wn   = wid % WN;
    const int m0 = blockIdx.y * BM;
    const int n0 = blockIdx.x * BN;
    const int r4 = lane >> 2;
    const int t  = lane & 3;

    constexpr int WARP_N = BN / WN;        // 32 or 40
    constexpr int NFRAG  = WARP_N / 8;     // 4 or 5
    const int BUFSZ = (BM + BN) * ROWB;

    float acc[2][NFRAG][4];
#pragma unroll
    for (int i = 0; i < 2; i++)
#pragma unroll
        for (int j = 0; j < NFRAG; j++)
#pragma unroll
            for (int q = 0; q < 4; q++) acc[i][j][q] = 0.f;

    auto load_stage = [&](int s) {
        const int buf = s & 1;
        const int k0 = s * 32;
        uint32_t base = sbase + buf * BUFSZ;
#pragma unroll
        for (int i = tid; i < BM * 4; i += THREADS) {
            int row = i >> 2, seg = i & 3;
            pd_cp16(base + row * ROWB + seg * 16,
                    Ahi + (size_t)(m0 + row) * EMB + k0 + seg * 8);
        }
#pragma unroll 2
        for (int i = tid; i < BN * 4; i += THREADS) {
            int row = i >> 2, seg = i & 3;
            pd_cp16(base + BM * ROWB + row * ROWB + seg * 16,
                    Bhi + (size_t)(n0 + row) * EMB + k0 + seg * 8);
        }
        pd_cp_commit();
    };

    load_stage(0);

    for (int s = 0; s < NSTG; s++) {
        if (s + 1 < NSTG) { load_stage(s + 1); pd_cp_wait(1); }
        else              pd_cp_wait(0);
        __syncthreads();

        const int buf = s & 1;
        const char* sa = sm + buf * BUFSZ;
        const char* sb = sm + buf * BUFSZ + BM * ROWB;

#pragma unroll
        for (int kk = 0; kk < 2; kk++) {
            uint32_t Ah[2][4], Bh[NFRAG][2];
#pragma unroll
            for (int i = 0; i < 2; i++) {
                uint32_t off = (uint32_t)((wm * 32 + i * 16 + r4) * ROWB + t * 4 + kk * 32);
                Ah[i][0] = *(const uint32_t*)(sa + off);
                Ah[i][1] = *(const uint32_t*)(sa + off + 8 * ROWB);
                Ah[i][2] = *(const uint32_t*)(sa + off + 16);
                Ah[i][3] = *(const uint32_t*)(sa + off + 8 * ROWB + 16);
            }
#pragma unroll
            for (int j = 0; j < NFRAG; j++) {
                uint32_t off = (uint32_t)((wn * WARP_N + j * 8 + r4) * ROWB + t * 4 + kk * 32);
                Bh[j][0] = *(const uint32_t*)(sb + off);
                Bh[j][1] = *(const uint32_t*)(sb + off + 16);
            }
#pragma unroll
            for (int i = 0; i < 2; i++)
#pragma unroll
                for (int j = 0; j < NFRAG; j++)
                    pd_mma_fp16(acc[i][j], Ah[i], Bh[j]);
        }
        __syncthreads();
    }

#pragma unroll
    for (int i = 0; i < 2; i++) {
        int row = m0 + wm * 32 + i * 16 + r4;
#pragma unroll
        for (int j = 0; j < NFRAG; j++) {
            int col = n0 + wn * WARP_N + j * 8 + t * 2;
            *(float2*)(C + (size_t)row * ldc + col)       = make_float2(acc[i][j][0], acc[i][j][1]);
            *(float2*)(C + (size_t)(row + 8) * ldc + col) = make_float2(acc[i][j][2], acc[i][j][3]);
        }
    }
}

// ---------------- pos_term = rel_pos_emb @ W_pos  (64x16) ----------------
__global__ void pos_kernel(const float* __restrict__ rel, const float* __restrict__ Wp)
{
    int i = threadIdx.x;
    if (i < DELTA * BD) {
        int j = i >> 4, c = i & 15;
        float s = 0.f;
#pragma unroll
        for (int k = 0; k < BD; k++)
            s = fmaf(rel[j * BD + k], Wp[k * BD + c], s);
        g_pos[i] = s;
    }
}

// ---------------- fused window attention: fp16 phase2 + HMMA phase3 --------
#define VSTRIDE 72      // halfs per val row (144 B, 16B-multiple)
#define PBSTRIDE 88     // halfs per PB row (176 B, 16B-multiple)

__global__ __launch_bounds__(512) void fused_kernel(
    const float* __restrict__ W_strain, const float* __restrict__ W_dmg,
    const float* __restrict__ b_dmg,    const float* __restrict__ W_bond,
    const float* __restrict__ W_dmg_out, const float* __restrict__ b_dmg_out)
{
    __shared__ __align__(16) __half s_vh[80 * VSTRIDE];   // 11.25 KB
    __shared__ __align__(16) __half s_vl[80 * VSTRIDE];   // 11.25 KB
    __shared__ float   s_disp[NROWS * BD];                // 5.1 KB
    __shared__ float2  s_W2 [BD * 16];                    // 2 KB
    __shared__ __half2 s_PT [16 * NROWS];                 // 5.1 KB  [c][r] (bond,dmg)
    __shared__ __half2 s_ppT[16 * DELTA];                 // 4 KB    [c][j] (pos,b_dmg)
    __shared__ __align__(16) __half s_PBh[16 * PBSTRIDE]; // 2.8 KB
    __shared__ __align__(16) __half s_PBl[16 * PBSTRIDE]; // 2.8 KB
    __shared__ __half2 s_wout2[16];
    __shared__ float   s_inv[16];

    const int b  = blockIdx.z;
    const int h  = blockIdx.y;
    const int t0 = blockIdx.x * TTILE;
    const int tid = threadIdx.x;
    const int base_s = t0 - (DELTA - 1);

    // ---- phase 0: loads + zero-init ----
    for (int i = tid; i < NROWS * (HS / 4); i += 512) {
        int r  = i >> 4;
        int c4 = (i & 15) * 4;
        int s  = base_s + r;
        float4 v = make_float4(0.f, 0.f, 0.f, 0.f);
        if (s >= 0)
            v = *(const float4*)(g_dv + (size_t)(b * SEQ + s) * NDV + 256 + h * HS + c4);
        uint32_t h01, l01, h23, l23;
        pd_split2h(v.x, v.y, h01, l01);
        pd_split2h(v.z, v.w, h23, l23);
        *(uint2*)(&s_vh[r * VSTRIDE + c4]) = make_uint2(h01, h23);
        *(uint2*)(&s_vl[r * VSTRIDE + c4]) = make_uint2(l01, l23);
    }
    if (tid < 32) {   // zero pad row 79 of val window
        *(uint32_t*)(&s_vh[79 * VSTRIDE + tid * 2]) = 0;
        *(uint32_t*)(&s_vl[79 * VSTRIDE + tid * 2]) = 0;
    }
    for (int i = tid; i < (16 * PBSTRIDE) / 2; i += 512) {
        *(uint32_t*)(&s_PBh[2 * i]) = 0;
        *(uint32_t*)(&s_PBl[2 * i]) = 0;
    }
    for (int i = tid; i < NROWS * (BD / 4); i += 512) {
        int r  = i >> 2;
        int c4 = (i & 3) * 4;
        int s  = base_s + r;
        float4 v = make_float4(0.f, 0.f, 0.f, 0.f);
        if (s >= 0)
            v = *(const float4*)(g_dv + (size_t)(b * SEQ + s) * NDV + h * BD + c4);
        *(float4*)(s_disp + r * BD + c4) = v;
    }
    if (tid < BD * 16)
        s_W2[tid] = make_float2(W_strain[tid], W_dmg[tid]);
    if (tid < 16)
        s_wout2[tid] = __floats2half2_rn(0.5f * W_bond[tid], 0.5f * W_dmg_out[tid]);
    for (int i = tid; i < 16 * DELTA; i += 512) {
        int c = i >> 6, j = i & 63;
        s_ppT[i] = __floats2half2_rn(g_pos[j * BD + c], b_dmg[c]);
    }
    __syncthreads();

    // ---- phase 1: PT[c][r] = (disp_r . Ws_c, disp_r . Wd_c) as half2 ----
    for (int i = tid; i < NROWS * 16; i += 512) {
        int r = i >> 4, c = i & 15;
        u64 acc = 0;
#pragma unroll
        for (int k = 0; k < BD; k++)
            acc = pd_fma2(pd_dupf(s_disp[r * BD + k]), *(const u64*)(&s_W2[k * 16 + c]), acc);
        float sx, sy; pd_unpack2(acc, sx, sy);
        s_PT[c * NROWS + r] = __floats2half2_rn(sx, sy);
    }
    __syncthreads();

    // ---- phase 2: logits (lane = j; two halves j, j+32), fp16 math ----
    const int wid  = tid >> 5;
    const int lane = tid & 31;
    const int t    = t0 + wid;

    const __half2 C0h = __float2half2_rn(0.7978845608f);
    const __half2 C1h = __float2half2_rn(0.0356774081f);
    const float c0  = 0.5f * b_dmg_out[0];
    const float L2E = 1.44269504089f, N5L2E = -7.21347520444f;

    __half2 accA = __float2half2_rn(0.f);
    __half2 accB = accA;

#pragma unroll
    for (int c = 0; c < 16; c++) {
        const __half2* Pc  = &s_PT[c * NROWS + wid];
        const __half2* ppc = &s_ppT[c * DELTA];
        const __half2 pre = Pc[DELTA - 1];
        const __half2 w2  = s_wout2[c];
        {
            __half2 xx = __hsub2(__hadd2(Pc[lane], ppc[lane]), pre);
            __half2 u  = __hmul2(xx, xx);
            __half2 t1 = __hfma2(u, C1h, C0h);
            __half2 th = pd_tanh2(__hmul2(xx, t1));
            __half2 m  = __hfma2(th, xx, xx);
            accA = __hfma2(m, w2, accA);
        }
        {
            __half2 xx = __hsub2(__hadd2(Pc[lane + 32], ppc[lane + 32]), pre);
            __half2 u  = __hmul2(xx, xx);
            __half2 t1 = __hfma2(u, C1h, C0h);
            __half2 th = pd_tanh2(__hmul2(xx, t1));
            __half2 m  = __hfma2(th, xx, xx);
            accB = __hfma2(m, w2, accB);
        }
    }

    const int jstart = (t < DELTA - 1) ? (DELTA - 1 - t) : 0;

    float p0, p1;
    {
        float bond = __low2float(accA), dm = __high2float(accA);
        float th2 = pd_tanhf(fmaf(dm, 0.5f, c0));
        float lt  = fmaf(th2, -5.f, bond);
        p0 = pd_ex2(fmaf(lt, L2E, N5L2E));
        if (lane < jstart) p0 = 0.f;
    }
    {
        float bond = __low2float(accB), dm = __high2float(accB);
        float th2 = pd_tanhf(fmaf(dm, 0.5f, c0));
        float lt  = fmaf(th2, -5.f, bond);
        p1 = pd_ex2(fmaf(lt, L2E, N5L2E));
        if (lane + 32 < jstart) p1 = 0.f;
    }

    // scatter p (hi + residual) into PB band
    {
        __half ph0 = __float2half_rn(p0);
        __half pl0 = __float2half_rn(p0 - __half2float(ph0));
        __half ph1 = __float2half_rn(p1);
        __half pl1 = __float2half_rn(p1 - __half2float(ph1));
        int bcol = wid * PBSTRIDE + wid + lane;
        s_PBh[bcol] = ph0;       s_PBl[bcol] = pl0;
        s_PBh[bcol + 32] = ph1;  s_PBl[bcol + 32] = pl1;
    }

    float ssum = p0 + p1;
#pragma unroll
    for (int off = 1; off < 32; off <<= 1)
        ssum += __shfl_xor_sync(0xffffffffu, ssum, off);
    if (lane == 0)
        s_inv[wid] = __fdividef(1.0f, ssum);
    __syncthreads();

    // ---- phase 3: out[16][64] = PB[16][80] x val[80][64] via HMMA ----
    if (wid < 8) {
        const int nb = wid;
        float acc[4] = {0.f, 0.f, 0.f, 0.f};
        const uint32_t pbh = pd_smem_u32(s_PBh), pbl = pd_smem_u32(s_PBl);
        const uint32_t vhb = pd_smem_u32(s_vh),  vlb = pd_smem_u32(s_vl);
        const uint32_t rA = (uint32_t)(lane & 15);
        const uint32_t cA = (uint32_t)((lane >> 4) * 8);
#pragma unroll
        for (int kk = 0; kk < 5; kk++) {
            uint32_t offA = (rA * PBSTRIDE + kk * 16 + cA) * 2;
            uint32_t offB = ((kk * 16 + (lane & 15)) * VSTRIDE + nb * 8) * 2;
            uint32_t Ah[4], Al[4], Bh[2], Bl[2];
            PD_LDSM_X4(Ah, pbh + offA);
            PD_LDSM_X4(Al, pbl + offA);
            PD_LDSM_X2T(Bh, vhb + offB);
            PD_LDSM_X2T(Bl, vlb + offB);
            pd_mma_fp16(acc, Ah, Bh);
            pd_mma_fp16(acc, Ah, Bl);
            pd_mma_fp16(acc, Al, Bh);
        }
        const int r0 = lane >> 2;
        const int e  = nb * 8 + (lane & 3) * 2;
        const float inv0 = s_inv[r0], inv1 = s_inv[r0 + 8];
        size_t ob0 = (size_t)(b * SEQ + t0 + r0) * EMB + h * HS + e;
        *(__half2*)(&g_athi[ob0]) = __floats2half2_rn(acc[0] * inv0, acc[1] * inv0);
        size_t ob1 = ob0 + (size_t)8 * EMB;
        *(__half2*)(&g_athi[ob1]) = __floats2half2_rn(acc[2] * inv1, acc[3] * inv1);
    }
}

// ---------------- launch ----------------
extern "C" void kernel_launch(void* const* d_in, const int* in_sizes, int n_in,
                              void* d_out, int out_size)
{
    const float* x         = (const float*)d_in[0];
    const float* W_disp    = (const float*)d_in[1];
    const float* W_val     = (const float*)d_in[2];
    const float* rel       = (const float*)d_in[3];
    const float* W_strain  = (const float*)d_in[4];
    const float* W_pos     = (const float*)d_in[5];
    const float* W_bond    = (const float*)d_in[6];
    const float* W_dmg     = (const float*)d_in[7];
    const float* b_dmg     = (const float*)d_in[8];
    const float* W_dmg_out = (const float*)d_in[9];
    const float* b_dmg_out = (const float*)d_in[10];
    const float* W_cproj   = (const float*)d_in[11];
    float* out = (float*)d_out;

    float* dv_p;
    __half *xhi, *athi, *bthi, *cthi;
    cudaGetSymbolAddress((void**)&dv_p, g_dv);
    cudaGetSymbolAddress((void**)&xhi, g_xhi);
    cudaGetSymbolAddress((void**)&athi, g_athi);
    cudaGetSymbolAddress((void**)&bthi, g_bthi);
    cudaGetSymbolAddress((void**)&cthi, g_cthi);

    const int SMEM_DV = (128 + 160) * ROWB * 2;   // 46080
    const int SMEM_CP = (128 + 128) * ROWB * 2;   // 40960
    cudaFuncSetAttribute((const void*)gemm_kernel<128, 160, 512, 4>,
                         cudaFuncAttributeMaxDynamicSharedMemorySize, SMEM_DV);
    cudaFuncSetAttribute((const void*)gemm_kernel<128, 128, 512, 4>,
                         cudaFuncAttributeMaxDynamicSharedMemorySize, SMEM_CP);

    pos_kernel<<<1, 1024>>>(rel, W_pos);
    split_x_kernel<<<(MTOT * EMB / 4) / 512, 512>>>(x);
    splitT_kernel<<<dim3(2304 / 32, EMB / 32), dim3(32, 8)>>>(W_disp, W_val, W_cproj);

    // combined disp+val GEMM: C[2048][1280] = x * [W_disp | W_val]; 128 CTAs = 1 wave
    gemm_kernel<128, 160, 512, 4><<<dim3(NDV / 160, MTOT / 128), 512, SMEM_DV>>>(
        xhi, bthi, dv_p, NDV);
    fused_kernel<<<dim3(SEQ / TTILE, NH, BATCH), 512>>>(W_strain, W_dmg, b_dmg,
                                                        W_bond, W_dmg_out, b_dmg_out);
    gemm_kernel<128, 128, 512, 4><<<dim3(EMB / 128, MTOT / 128), 512, SMEM_CP>>>(
        athi, cthi, out, EMB);
}

// round 13
// speedup vs baseline: 5.8322x; 1.1764x over previous
#include <cuda_runtime.h>
#include <cuda_fp16.h>
#include <cstdint>
#include <math.h>

#define BATCH 2
#define SEQ   1024
#define EMB   1024
#define NH    16
#define HS    64
#define BD    16
#define DELTA 64
#define TTILE 32
#define NROWS (TTILE + DELTA - 1)   // 95
#define MTOT  (BATCH * SEQ)         // 2048
#define NDV   1280                  // disp (256) ++ val (1024) columns

// ---------------- scratch (static device memory; no allocs) ----------------
__device__ float g_dv [MTOT * NDV];                // [disp | val] fp32
__device__ float g_pos[DELTA * BD];
__device__ __half g_xhi [MTOT * EMB];
__device__ __half g_athi[MTOT * EMB];
__device__ __half g_bthi[NDV * EMB];               // [W_disp^T ++ W_val^T]
__device__ __half g_cthi[EMB * EMB];               // W_cproj^T

// ---------------- helpers (pd_ prefix: no vendor-header collisions) --------
typedef unsigned long long u64;

__device__ __forceinline__ u64 pd_dupf(float v) {
    u64 r; asm("mov.b64 %0, {%1, %1};" : "=l"(r) : "f"(v)); return r;
}
__device__ __forceinline__ void pd_unpack2(u64 v, float& a, float& b) {
    asm("mov.b64 {%0, %1}, %2;" : "=f"(a), "=f"(b) : "l"(v));
}
__device__ __forceinline__ u64 pd_fma2(u64 a, u64 b, u64 c) {
    u64 r; asm("fma.rn.f32x2 %0, %1, %2, %3;" : "=l"(r) : "l"(a), "l"(b), "l"(c)); return r;
}
__device__ __forceinline__ float pd_tanhf(float x) {
    float r; asm("tanh.approx.f32 %0, %1;" : "=f"(r) : "f"(x)); return r;
}
__device__ __forceinline__ __half2 pd_tanh2(__half2 x) {
    uint32_t xi = *reinterpret_cast<uint32_t*>(&x), ri;
    asm("tanh.approx.f16x2 %0, %1;" : "=r"(ri) : "r"(xi));
    return *reinterpret_cast<__half2*>(&ri);
}
__device__ __forceinline__ float pd_ex2(float x) {
    float r; asm("ex2.approx.f32 %0, %1;" : "=f"(r) : "f"(x)); return r;
}
__device__ __forceinline__ uint32_t pd_smem_u32(const void* p) {
    uint32_t a;
    asm("{ .reg .u64 t; cvta.to.shared.u64 t, %1; cvt.u32.u64 %0, t; }" : "=r"(a) : "l"(p));
    return a;
}
__device__ __forceinline__ void pd_cp16(uint32_t dst, const void* src) {
    asm volatile("{ .reg .u64 g; cvta.to.global.u64 g, %1; cp.async.cg.shared.global [%0], [g], 16; }"
                 :: "r"(dst), "l"(src) : "memory");
}
__device__ __forceinline__ void pd_cp_commit() { asm volatile("cp.async.commit_group;" ::: "memory"); }
__device__ __forceinline__ void pd_cp_wait(int pending) {
    if (pending) asm volatile("cp.async.wait_group 1;" ::: "memory");
    else         asm volatile("cp.async.wait_group 0;" ::: "memory");
}

__device__ __forceinline__ void pd_split2h(float a, float b, uint32_t& hi, uint32_t& lo) {
    __half2 h2 = __floats2half2_rn(a, b);
    float ra = a - __half2float(h2.x);
    float rb = b - __half2float(h2.y);
    __half2 l2 = __floats2half2_rn(ra, rb);
    hi = *reinterpret_cast<uint32_t*>(&h2);
    lo = *reinterpret_cast<uint32_t*>(&l2);
}

__device__ __forceinline__ void pd_mma_fp16(float* c, const uint32_t* a, const uint32_t* b) {
    asm volatile(
        "mma.sync.aligned.m16n8k16.row.col.f32.f16.f16.f32 "
        "{%0,%1,%2,%3}, {%4,%5,%6,%7}, {%8,%9}, {%0,%1,%2,%3};"
        : "+f"(c[0]), "+f"(c[1]), "+f"(c[2]), "+f"(c[3])
        : "r"(a[0]), "r"(a[1]), "r"(a[2]), "r"(a[3]), "r"(b[0]), "r"(b[1]));
}

#define PD_LDSM_X4(r, a) \
    asm volatile("ldmatrix.sync.aligned.m8n8.x4.shared.b16 {%0,%1,%2,%3}, [%4];" \
                 : "=r"((r)[0]), "=r"((r)[1]), "=r"((r)[2]), "=r"((r)[3]) : "r"(a))
#define PD_LDSM_X2T(r, a) \
    asm volatile("ldmatrix.sync.aligned.m8n8.x2.trans.shared.b16 {%0,%1}, [%2];" \
                 : "=r"((r)[0]), "=r"((r)[1]) : "r"(a))

// ---------------- conversion kernels ----------------
__global__ __launch_bounds__(512) void split_x_kernel(const float* __restrict__ x) {
    size_t i = (size_t)blockIdx.x * 512 + threadIdx.x;   // over 512K float4
    float4 v = ((const float4*)x)[i];
    __half2 a = __floats2half2_rn(v.x, v.y);
    __half2 b = __floats2half2_rn(v.z, v.w);
    ((__half2*)g_xhi)[2 * i]     = a;
    ((__half2*)g_xhi)[2 * i + 1] = b;
}

__global__ void splitT_kernel(const float* __restrict__ Wd,
                              const float* __restrict__ Wv,
                              const float* __restrict__ Wc)
{
    __shared__ float tile[32][33];
    const int k0 = blockIdx.y * 32;
    const int n0 = blockIdx.x * 32;
    const int tx = threadIdx.x, ty = threadIdx.y;   // 32 x 8
#pragma unroll
    for (int q = 0; q < 4; q++) {
        int k = k0 + ty + 8 * q;
        int n = n0 + tx;
        float v;
        if (n < 256)        v = Wd[(size_t)k * 256 + n];
        else if (n < 1280)  v = Wv[(size_t)k * EMB + (n - 256)];
        else                v = Wc[(size_t)k * EMB + (n - 1280)];
        tile[ty + 8 * q][tx] = v;
    }
    __syncthreads();
#pragma unroll
    for (int q = 0; q < 4; q++) {
        int n = n0 + ty + 8 * q;
        int k = k0 + tx;
        __half hv = __float2half_rn(tile[tx][ty + 8 * q]);
        if (n < 1280) g_bthi[(size_t)n * EMB + k] = hv;
        else          g_cthi[(size_t)(n - 1280) * EMB + k] = hv;
    }
}

// ---------------- fp16 HMMA GEMM: K-chunk 64, double buffered ----------------
#define ROWB 144        // 64 halfs (128 B) + 16 B pad; (36i+t)%32 bank-permutation safe
#define KCH  64
#define NSTG (EMB / KCH)   // 16

template<int BM, int BN, int THREADS, int WN>
__global__ __launch_bounds__(THREADS) void gemm_kernel(
    const __half* __restrict__ Ahi, const __half* __restrict__ Bhi,
    float* __restrict__ C, int ldc)
{
    extern __shared__ __align__(16) char sm[];
    const uint32_t sbase = pd_smem_u32(sm);
    const int tid  = threadIdx.x;
    const int wid  = tid >> 5;
    const int lane = tid & 31;
    const int wm   = wid / WN;
    const int wn   = wid % WN;
    const int m0 = blockIdx.y * BM;
    const int n0 = blockIdx.x * BN;
    const int r4 = lane >> 2;
    const int t  = lane & 3;

    constexpr int WARP_N = BN / WN;        // 32 or 40
    constexpr int NFRAG  = WARP_N / 8;     // 4 or 5
    const int BUFSZ = (BM + BN) * ROWB;

    float acc[2][NFRAG][4];
#pragma unroll
    for (int i = 0; i < 2; i++)
#pragma unroll
        for (int j = 0; j < NFRAG; j++)
#pragma unroll
            for (int q = 0; q < 4; q++) acc[i][j][q] = 0.f;

    auto load_stage = [&](int s) {
        const int buf = s & 1;
        const int k0 = s * KCH;
        uint32_t base = sbase + buf * BUFSZ;
#pragma unroll 2
        for (int i = tid; i < BM * 8; i += THREADS) {
            int row = i >> 3, seg = i & 7;
            pd_cp16(base + row * ROWB + seg * 16,
                    Ahi + (size_t)(m0 + row) * EMB + k0 + seg * 8);
        }
#pragma unroll 3
        for (int i = tid; i < BN * 8; i += THREADS) {
            int row = i >> 3, seg = i & 7;
            pd_cp16(base + BM * ROWB + row * ROWB + seg * 16,
                    Bhi + (size_t)(n0 + row) * EMB + k0 + seg * 8);
        }
        pd_cp_commit();
    };

    load_stage(0);

    for (int s = 0; s < NSTG; s++) {
        if (s + 1 < NSTG) { load_stage(s + 1); pd_cp_wait(1); }
        else              pd_cp_wait(0);
        __syncthreads();

        const int buf = s & 1;
        const char* sa = sm + buf * BUFSZ;
        const char* sb = sm + buf * BUFSZ + BM * ROWB;

#pragma unroll
        for (int kk = 0; kk < 4; kk++) {
            uint32_t Ah[2][4], Bh[NFRAG][2];
#pragma unroll
            for (int i = 0; i < 2; i++) {
                uint32_t off = (uint32_t)((wm * 32 + i * 16 + r4) * ROWB + t * 4 + kk * 32);
                Ah[i][0] = *(const uint32_t*)(sa + off);
                Ah[i][1] = *(const uint32_t*)(sa + off + 8 * ROWB);
                Ah[i][2] = *(const uint32_t*)(sa + off + 16);
                Ah[i][3] = *(const uint32_t*)(sa + off + 8 * ROWB + 16);
            }
#pragma unroll
            for (int j = 0; j < NFRAG; j++) {
                uint32_t off = (uint32_t)((wn * WARP_N + j * 8 + r4) * ROWB + t * 4 + kk * 32);
                Bh[j][0] = *(const uint32_t*)(sb + off);
                Bh[j][1] = *(const uint32_t*)(sb + off + 16);
            }
#pragma unroll
            for (int i = 0; i < 2; i++)
#pragma unroll
                for (int j = 0; j < NFRAG; j++)
                    pd_mma_fp16(acc[i][j], Ah[i], Bh[j]);
        }
        __syncthreads();
    }

#pragma unroll
    for (int i = 0; i < 2; i++) {
        int row = m0 + wm * 32 + i * 16 + r4;
#pragma unroll
        for (int j = 0; j < NFRAG; j++) {
            int col = n0 + wn * WARP_N + j * 8 + t * 2;
            *(float2*)(C + (size_t)row * ldc + col)       = make_float2(acc[i][j][0], acc[i][j][1]);
            *(float2*)(C + (size_t)(row + 8) * ldc + col) = make_float2(acc[i][j][2], acc[i][j][3]);
        }
    }
}

// ---------------- pos_term = rel_pos_emb @ W_pos  (64x16) ----------------
__global__ void pos_kernel(const float* __restrict__ rel, const float* __restrict__ Wp)
{
    int i = threadIdx.x;
    if (i < DELTA * BD) {
        int j = i >> 4, c = i & 15;
        float s = 0.f;
#pragma unroll
        for (int k = 0; k < BD; k++)
            s = fmaf(rel[j * BD + k], Wp[k * BD + c], s);
        g_pos[i] = s;
    }
}

// ---------------- fused window attention: TTILE=32 ----------------
#define VSTRIDE 72       // halfs per val row (144 B)
#define PBSTRIDE 104     // halfs per PB row (208 B, 16B-multiple); 96 cols used

__global__ __launch_bounds__(512) void fused_kernel(
    const float* __restrict__ W_strain, const float* __restrict__ W_dmg,
    const float* __restrict__ b_dmg,    const float* __restrict__ W_bond,
    const float* __restrict__ W_dmg_out, const float* __restrict__ b_dmg_out)
{
    __shared__ __align__(16) __half s_vh[96 * VSTRIDE];    // 13.5 KB
    __shared__ __align__(16) __half s_vl[96 * VSTRIDE];    // 13.5 KB
    __shared__ float   s_disp[NROWS * BD];                 // 6.1 KB
    __shared__ float2  s_W2 [BD * 16];                     // 2 KB
    __shared__ __half2 s_PT [16 * NROWS];                  // 6.1 KB  [c][r]
    __shared__ __half2 s_ppT[16 * DELTA];                  // 4 KB    [c][j]
    __shared__ __align__(16) __half s_PBh[TTILE * PBSTRIDE]; // 6.5 KB
    __shared__ __align__(16) __half s_PBl[TTILE * PBSTRIDE]; // 6.5 KB
    __shared__ __half2 s_wout2[16];
    __shared__ float   s_inv[TTILE];

    const int b  = blockIdx.z;
    const int h  = blockIdx.y;
    const int t0 = blockIdx.x * TTILE;
    const int tid = threadIdx.x;
    const int base_s = t0 - (DELTA - 1);

    // ---- phase 0: loads + zero-init ----
    for (int i = tid; i < NROWS * (HS / 4); i += 512) {
        int r  = i >> 4;
        int c4 = (i & 15) * 4;
        int s  = base_s + r;
        float4 v = make_float4(0.f, 0.f, 0.f, 0.f);
        if (s >= 0)
            v = *(const float4*)(g_dv + (size_t)(b * SEQ + s) * NDV + 256 + h * HS + c4);
        uint32_t h01, l01, h23, l23;
        pd_split2h(v.x, v.y, h01, l01);
        pd_split2h(v.z, v.w, h23, l23);
        *(uint2*)(&s_vh[r * VSTRIDE + c4]) = make_uint2(h01, h23);
        *(uint2*)(&s_vl[r * VSTRIDE + c4]) = make_uint2(l01, l23);
    }
    if (tid < 32) {   // zero pad row 95 of val window
        *(uint32_t*)(&s_vh[95 * VSTRIDE + tid * 2]) = 0;
        *(uint32_t*)(&s_vl[95 * VSTRIDE + tid * 2]) = 0;
    }
    for (int i = tid; i < (TTILE * PBSTRIDE) / 2; i += 512) {
        *(uint32_t*)(&s_PBh[2 * i]) = 0;
        *(uint32_t*)(&s_PBl[2 * i]) = 0;
    }
    for (int i = tid; i < NROWS * (BD / 4); i += 512) {
        int r  = i >> 2;
        int c4 = (i & 3) * 4;
        int s  = base_s + r;
        float4 v = make_float4(0.f, 0.f, 0.f, 0.f);
        if (s >= 0)
            v = *(const float4*)(g_dv + (size_t)(b * SEQ + s) * NDV + h * BD + c4);
        *(float4*)(s_disp + r * BD + c4) = v;
    }
    if (tid < BD * 16)
        s_W2[tid] = make_float2(W_strain[tid], W_dmg[tid]);
    if (tid < 16)
        s_wout2[tid] = __floats2half2_rn(0.5f * W_bond[tid], 0.5f * W_dmg_out[tid]);
    for (int i = tid; i < 16 * DELTA; i += 512) {
        int c = i >> 6, j = i & 63;
        s_ppT[i] = __floats2half2_rn(g_pos[j * BD + c], b_dmg[c]);
    }
    __syncthreads();

    // ---- phase 1: PT[c][r] = (disp_r . Ws_c, disp_r . Wd_c) as half2 ----
    for (int i = tid; i < NROWS * 16; i += 512) {
        int r = i >> 4, c = i & 15;
        u64 acc = 0;
#pragma unroll
        for (int k = 0; k < BD; k++)
            acc = pd_fma2(pd_dupf(s_disp[r * BD + k]), *(const u64*)(&s_W2[k * 16 + c]), acc);
        float sx, sy; pd_unpack2(acc, sx, sy);
        s_PT[c * NROWS + r] = __floats2half2_rn(sx, sy);
    }
    __syncthreads();

    // ---- phase 2: logits; each warp handles t rows wid and wid+16 ----
    const int wid  = tid >> 5;
    const int lane = tid & 31;

    const __half2 C0h = __float2half2_rn(0.7978845608f);
    const __half2 C1h = __float2half2_rn(0.0356774081f);
    const float c0  = 0.5f * b_dmg_out[0];
    const float L2E = 1.44269504089f, N5L2E = -7.21347520444f;

#pragma unroll
    for (int half_t = 0; half_t < 2; half_t++) {
        const int tt = wid + half_t * 16;
        const int t  = t0 + tt;

        __half2 accA = __float2half2_rn(0.f);
        __half2 accB = accA;

#pragma unroll
        for (int c = 0; c < 16; c++) {
            const __half2* Pc  = &s_PT[c * NROWS + tt];
            const __half2* ppc = &s_ppT[c * DELTA];
            const __half2 pre = Pc[DELTA - 1];
            const __half2 w2  = s_wout2[c];
            {
                __half2 xx = __hsub2(__hadd2(Pc[lane], ppc[lane]), pre);
                __half2 u  = __hmul2(xx, xx);
                __half2 t1 = __hfma2(u, C1h, C0h);
                __half2 th = pd_tanh2(__hmul2(xx, t1));
                __half2 m  = __hfma2(th, xx, xx);
                accA = __hfma2(m, w2, accA);
            }
            {
                __half2 xx = __hsub2(__hadd2(Pc[lane + 32], ppc[lane + 32]), pre);
                __half2 u  = __hmul2(xx, xx);
                __half2 t1 = __hfma2(u, C1h, C0h);
                __half2 th = pd_tanh2(__hmul2(xx, t1));
                __half2 m  = __hfma2(th, xx, xx);
                accB = __hfma2(m, w2, accB);
            }
        }

        const int jstart = (t < DELTA - 1) ? (DELTA - 1 - t) : 0;

        float p0, p1;
        {
            float bond = __low2float(accA), dm = __high2float(accA);
            float th2 = pd_tanhf(fmaf(dm, 0.5f, c0));
            float lt  = fmaf(th2, -5.f, bond);
            p0 = pd_ex2(fmaf(lt, L2E, N5L2E));
            if (lane < jstart) p0 = 0.f;
        }
        {
            float bond = __low2float(accB), dm = __high2float(accB);
            float th2 = pd_tanhf(fmaf(dm, 0.5f, c0));
            float lt  = fmaf(th2, -5.f, bond);
            p1 = pd_ex2(fmaf(lt, L2E, N5L2E));
            if (lane + 32 < jstart) p1 = 0.f;
        }

        {
            __half ph0 = __float2half_rn(p0);
            __half pl0 = __float2half_rn(p0 - __half2float(ph0));
            __half ph1 = __float2half_rn(p1);
            __half pl1 = __float2half_rn(p1 - __half2float(ph1));
            int bcol = tt * PBSTRIDE + tt + lane;
            s_PBh[bcol] = ph0;       s_PBl[bcol] = pl0;
            s_PBh[bcol + 32] = ph1;  s_PBl[bcol + 32] = pl1;
        }

        float ssum = p0 + p1;
#pragma unroll
        for (int off = 1; off < 32; off <<= 1)
            ssum += __shfl_xor_sync(0xffffffffu, ssum, off);
        if (lane == 0)
            s_inv[tt] = __fdividef(1.0f, ssum);
    }
    __syncthreads();

    // ---- phase 3: out[32][64] = PB[32][96] x val[96][64]; 16 warps ----
    {
        const int mhalf = wid >> 3;          // 0: t rows 0-15, 1: rows 16-31
        const int nb    = wid & 7;           // 8-col output block
        const int rowbase = mhalf * 16;
        float acc[4] = {0.f, 0.f, 0.f, 0.f};
        const uint32_t pbh = pd_smem_u32(s_PBh), pbl = pd_smem_u32(s_PBl);
        const uint32_t vhb = pd_smem_u32(s_vh),  vlb = pd_smem_u32(s_vl);
        const uint32_t rA = (uint32_t)(lane & 15);
        const uint32_t cA = (uint32_t)((lane >> 4) * 8);
#pragma unroll
        for (int kk = 0; kk < 5; kk++) {
            uint32_t offA = ((rowbase + rA) * PBSTRIDE + rowbase + kk * 16 + cA) * 2;
            uint32_t offB = ((rowbase + kk * 16 + (lane & 15)) * VSTRIDE + nb * 8) * 2;
            uint32_t Ah[4], Al[4], Bh[2], Bl[2];
            PD_LDSM_X4(Ah, pbh + offA);
            PD_LDSM_X4(Al, pbl + offA);
            PD_LDSM_X2T(Bh, vhb + offB);
            PD_LDSM_X2T(Bl, vlb + offB);
            pd_mma_fp16(acc, Ah, Bh);
            pd_mma_fp16(acc, Ah, Bl);
            pd_mma_fp16(acc, Al, Bh);
        }
        const int r0 = lane >> 2;
        const int e  = nb * 8 + (lane & 3) * 2;
        const float inv0 = s_inv[rowbase + r0], inv1 = s_inv[rowbase + r0 + 8];
        size_t ob0 = (size_t)(b * SEQ + t0 + rowbase + r0) * EMB + h * HS + e;
        *(__half2*)(&g_athi[ob0]) = __floats2half2_rn(acc[0] * inv0, acc[1] * inv0);
        size_t ob1 = ob0 + (size_t)8 * EMB;
        *(__half2*)(&g_athi[ob1]) = __floats2half2_rn(acc[2] * inv1, acc[3] * inv1);
    }
}

// ---------------- launch ----------------
extern "C" void kernel_launch(void* const* d_in, const int* in_sizes, int n_in,
                              void* d_out, int out_size)
{
    const float* x         = (const float*)d_in[0];
    const float* W_disp    = (const float*)d_in[1];
    const float* W_val     = (const float*)d_in[2];
    const float* rel       = (const float*)d_in[3];
    const float* W_strain  = (const float*)d_in[4];
    const float* W_pos     = (const float*)d_in[5];
    const float* W_bond    = (const float*)d_in[6];
    const float* W_dmg     = (const float*)d_in[7];
    const float* b_dmg     = (const float*)d_in[8];
    const float* W_dmg_out = (const float*)d_in[9];
    const float* b_dmg_out = (const float*)d_in[10];
    const float* W_cproj   = (const float*)d_in[11];
    float* out = (float*)d_out;

    float* dv_p;
    __half *xhi, *athi, *bthi, *cthi;
    cudaGetSymbolAddress((void**)&dv_p, g_dv);
    cudaGetSymbolAddress((void**)&xhi, g_xhi);
    cudaGetSymbolAddress((void**)&athi, g_athi);
    cudaGetSymbolAddress((void**)&bthi, g_bthi);
    cudaGetSymbolAddress((void**)&cthi, g_cthi);

    const int SMEM_DV = (128 + 160) * ROWB * 2;   // 82944
    const int SMEM_CP = (128 + 128) * ROWB * 2;   // 73728
    cudaFuncSetAttribute((const void*)gemm_kernel<128, 160, 512, 4>,
                         cudaFuncAttributeMaxDynamicSharedMemorySize, SMEM_DV);
    cudaFuncSetAttribute((const void*)gemm_kernel<128, 128, 512, 4>,
                         cudaFuncAttributeMaxDynamicSharedMemorySize, SMEM_CP);

    pos_kernel<<<1, 1024>>>(rel, W_pos);
    split_x_kernel<<<(MTOT * EMB / 4) / 512, 512>>>(x);
    splitT_kernel<<<dim3(2304 / 32, EMB / 32), dim3(32, 8)>>>(W_disp, W_val, W_cproj);

    gemm_kernel<128, 160, 512, 4><<<dim3(NDV / 160, MTOT / 128), 512, SMEM_DV>>>(
        xhi, bthi, dv_p, NDV);
    fused_kernel<<<dim3(SEQ / TTILE, NH, BATCH), 512>>>(W_strain, W_dmg, b_dmg,
                                                        W_bond, W_dmg_out, b_dmg_out);
    gemm_kernel<128, 128, 512, 4><<<dim3(EMB / 128, MTOT / 128), 512, SMEM_CP>>>(
        athi, cthi, out, EMB);
}